// round 12
// baseline (speedup 1.0000x reference)
#include <cuda_runtime.h>
#include <cuda_bf16.h>
#include <cuda_fp16.h>
#include <stdint.h>
#include <math.h>

#define NB 8
#define NH 8
#define SEQ 512
#define HID 512
#define HD 64

// ---------------- scratch (device globals; no allocations) ----------------
__device__ float g_maskf[NB*SEQ];                        // 0/1 floats
__device__ __half g_biasf[(size_t)NB*NH*SEQ*SEQ];        // 32 MB fp16 bias (+key mask)
__device__ __half g_Qf[NB*NH*SEQ*HD];                    // [b,h,n,d] (pre-scaled)
__device__ __half g_Kf[NB*NH*SEQ*HD];                    // [b,h,n,d]
__device__ __half g_VTf[NB*NH*SEQ*HD];                   // [b,h,d,n]
__device__ __nv_bfloat16 g_Ahi[NB*SEQ*HID], g_Alo[NB*SEQ*HID];   // x / ctx
__device__ __nv_bfloat16 g_WThi[4][HID*HID], g_WTlo[4][HID*HID]; // W^T [n][k]
__device__ int g_ready[32];                              // per (b,qb) head counters

// ---------------- PTX helpers ----------------
__device__ __forceinline__ uint32_t sm_u32(const void* p) {
    return (uint32_t)__cvta_generic_to_shared(p);
}
#define CP16(dst_u32, gptr) \
    asm volatile("cp.async.ca.shared.global [%0], [%1], 16;" :: "r"(dst_u32), "l"(gptr))
#define CP_COMMIT() asm volatile("cp.async.commit_group;")
#define CP_WAIT0()  asm volatile("cp.async.wait_group 0;")
#define LDMX4(r, addr) \
    asm volatile("ldmatrix.sync.aligned.m8n8.x4.shared.b16 {%0,%1,%2,%3}, [%4];" \
        : "=r"((r)[0]), "=r"((r)[1]), "=r"((r)[2]), "=r"((r)[3]) : "r"(addr))
#define MMA16816(d, a, b) \
    asm volatile("mma.sync.aligned.m16n8k16.row.col.f32.bf16.bf16.f32 " \
        "{%0,%1,%2,%3},{%4,%5,%6,%7},{%8,%9},{%0,%1,%2,%3};\n" \
        : "+f"((d)[0]), "+f"((d)[1]), "+f"((d)[2]), "+f"((d)[3]) \
        : "r"((a)[0]), "r"((a)[1]), "r"((a)[2]), "r"((a)[3]), "r"((b)[0]), "r"((b)[1]))
#define MMA16816H(d, a, b) \
    asm volatile("mma.sync.aligned.m16n8k16.row.col.f32.f16.f16.f32 " \
        "{%0,%1,%2,%3},{%4,%5,%6,%7},{%8,%9},{%0,%1,%2,%3};\n" \
        : "+f"((d)[0]), "+f"((d)[1]), "+f"((d)[2]), "+f"((d)[3]) \
        : "r"((a)[0]), "r"((a)[1]), "r"((a)[2]), "r"((a)[3]), "r"((b)[0]), "r"((b)[1]))

// split pair (a=elem0, b=elem1) into packed bf16x2 hi and lo residual
__device__ __forceinline__ void split2(float a, float b, uint32_t& hi, uint32_t& lo) {
    __nv_bfloat16 ha = __float2bfloat16(a), hb = __float2bfloat16(b);
    __nv_bfloat16 la = __float2bfloat16(a - __bfloat162float(ha));
    __nv_bfloat16 lb = __float2bfloat16(b - __bfloat162float(hb));
    hi = ((uint32_t)__bfloat16_as_ushort(hb) << 16) | (uint32_t)__bfloat16_as_ushort(ha);
    lo = ((uint32_t)__bfloat16_as_ushort(lb) << 16) | (uint32_t)__bfloat16_as_ushort(la);
}

__device__ __forceinline__ uint32_t packh2(float a, float b) {
    __half2 h = __floats2half2_rn(a, b);
    return *reinterpret_cast<uint32_t*>(&h);
}

// ================= prep_x: x -> hi/lo bf16 split ==============
__global__ __launch_bounds__(256) void prep_x_kernel(const float* __restrict__ x) {
    int i = blockIdx.x * 256 + threadIdx.x;     // over float4s (2M floats)
    float4 v = ((const float4*)x)[i];
    uint32_t h0, l0, h1, l1;
    split2(v.x, v.y, h0, l0);
    split2(v.z, v.w, h1, l1);
    uint32_t* hp = (uint32_t*)(g_Ahi + 4*(size_t)i);
    uint32_t* lp = (uint32_t*)(g_Alo + 4*(size_t)i);
    hp[0] = h0; hp[1] = h1;
    lp[0] = l0; lp[1] = l1;
}

// ================= prep_w: W^T hi/lo + mask + ready-counter reset ==========
__global__ __launch_bounds__(256) void prep_w_kernel(
    const float* __restrict__ Wq, const float* __restrict__ Wk,
    const float* __restrict__ Wv, const float* __restrict__ Wo,
    const unsigned char* __restrict__ raw)
{
    __shared__ float t[32][33];
    __shared__ int mode;
    const int bx = blockIdx.x;
    const int tid = threadIdx.x;

    if (bx < 1024) {
        // ---- W -> W^T hi/lo (32x32 tile transpose) ----
        const int z = bx >> 8;
        const int bxx = bx & 15, byy = (bx >> 4) & 15;
        const float* W = (z == 0) ? Wq : (z == 1) ? Wk : (z == 2) ? Wv : Wo;
        __nv_bfloat16* Th = g_WThi[z];
        __nv_bfloat16* Tl = g_WTlo[z];
        int tx = tid & 31, ty = tid >> 5;       // 32 x 8
        int n0 = bxx * 32, k0 = byy * 32;
        #pragma unroll
        for (int j = 0; j < 4; j++)
            t[ty + 8*j][tx] = W[(size_t)(k0 + ty + 8*j) * HID + n0 + tx];
        __syncthreads();
        #pragma unroll
        for (int j = 0; j < 4; j++) {
            float v = t[tx][ty + 8*j];
            __nv_bfloat16 h = __float2bfloat16(v);
            __nv_bfloat16 l = __float2bfloat16(v - __bfloat162float(h));
            size_t o = (size_t)(n0 + ty + 8*j) * HID + k0 + tx;
            Th[o] = h;
            Tl[o] = l;
        }
    } else {
        // ---- mask normalization (dtype-agnostic) + zero ready counters ----
        if (tid < 32) g_ready[tid] = 0;
        if (tid == 0) {
            const unsigned int* w = (const unsigned int*)raw;
            int cf = 0, byteish = 0;
            for (int i = 0; i < 128; i++) {
                unsigned int v = w[i];
                if (v == 0x3F800000u) cf++;
                bool b01 = true;
                #pragma unroll
                for (int bb = 0; bb < 4; bb++) {
                    unsigned int by = (v >> (8*bb)) & 0xFFu;
                    if (by > 1u) b01 = false;
                }
                if (b01 && v > 1u) byteish++;
            }
            mode = (cf > 64) ? 0 : ((byteish > 0) ? 2 : 1);  // 0=f32, 1=i32, 2=u8
        }
        __syncthreads();
        int md = mode;
        for (int i = tid; i < NB*SEQ; i += 256) {
            float m;
            if (md == 0)      m = (((const float*)raw)[i] != 0.0f) ? 1.0f : 0.0f;
            else if (md == 1) m = (((const int*)raw)[i]   != 0)    ? 1.0f : 0.0f;
            else              m = (raw[i]                 != 0)    ? 1.0f : 0.0f;
            g_maskf[i] = m;
        }
    }
}

// ================= bf16x3 tensor-core GEMM core (verified R4) =============
#define GBK 32
#define LDT 40
#define BUF_ELEMS (128 * LDT)
#define AH_OFS 0
#define ALO_OFS (2 * BUF_ELEMS)
#define BH_OFS  (4 * BUF_ELEMS)
#define BLO_OFS (6 * BUF_ELEMS)
#define GEMM_SMEM_BYTES (8 * BUF_ELEMS * 2)

__device__ __forceinline__ void bf16x3_gemm(
    const __nv_bfloat16* __restrict__ Ahi, const __nv_bfloat16* __restrict__ Alo,
    const __nv_bfloat16* __restrict__ Bhi, const __nv_bfloat16* __restrict__ Blo,
    int m0, int n0, __nv_bfloat16* sm, float acc[4][4][4])
{
    const int tid = threadIdx.x;
    const int lane = tid & 31, wid = tid >> 5;
    const int wm = wid >> 2, wn = wid & 3;
    const uint32_t smb = sm_u32(sm);

    #pragma unroll
    for (int mi = 0; mi < 4; mi++)
        #pragma unroll
        for (int ni = 0; ni < 4; ni++)
            #pragma unroll
            for (int r = 0; r < 4; r++) acc[mi][ni][r] = 0.0f;

    const int c0 = tid, c1 = tid + 256;
    const int r0 = c0 >> 2, s0 = c0 & 3;
    const int r1 = c1 >> 2, s1 = c1 & 3;

    auto load_chunk = [&](int kc, int buf) {
        const int k0 = kc * GBK;
        const uint32_t so0 = (uint32_t)(buf * BUF_ELEMS + r0 * LDT + s0 * 8) * 2;
        const uint32_t so1 = (uint32_t)(buf * BUF_ELEMS + r1 * LDT + s1 * 8) * 2;
        const size_t ga0 = (size_t)(m0 + r0) * HID + k0 + s0 * 8;
        const size_t ga1 = (size_t)(m0 + r1) * HID + k0 + s1 * 8;
        const size_t gb0 = (size_t)(n0 + r0) * HID + k0 + s0 * 8;
        const size_t gb1 = (size_t)(n0 + r1) * HID + k0 + s1 * 8;
        CP16(smb + AH_OFS*2  + so0, Ahi + ga0);
        CP16(smb + AH_OFS*2  + so1, Ahi + ga1);
        CP16(smb + ALO_OFS*2 + so0, Alo + ga0);
        CP16(smb + ALO_OFS*2 + so1, Alo + ga1);
        CP16(smb + BH_OFS*2  + so0, Bhi + gb0);
        CP16(smb + BH_OFS*2  + so1, Bhi + gb1);
        CP16(smb + BLO_OFS*2 + so0, Blo + gb0);
        CP16(smb + BLO_OFS*2 + so1, Blo + gb1);
    };

    const int arow = wm * 64 + (lane & 15);
    const int acolb = (lane >> 4) << 3;
    const int brow = wn * 32 + (lane & 7) + ((lane & 16) >> 1);
    const int bcolb = lane & 8;

    load_chunk(0, 0);
    CP_COMMIT();

    for (int kc = 0; kc < HID / GBK; kc++) {
        CP_WAIT0();
        __syncthreads();
        if (kc + 1 < HID / GBK) {
            load_chunk(kc + 1, (kc + 1) & 1);
            CP_COMMIT();
        }
        const int buf = kc & 1;
        #pragma unroll
        for (int ks = 0; ks < 2; ks++) {
            uint32_t ah[4][4], al[4][4], bh[2][4], bl[2][4];
            const int acol = ks * 16 + acolb;
            const int bcol = ks * 16 + bcolb;
            #pragma unroll
            for (int mi = 0; mi < 4; mi++) {
                uint32_t off = (uint32_t)(buf * BUF_ELEMS + (arow + mi*16) * LDT + acol) * 2;
                LDMX4(ah[mi], smb + AH_OFS*2 + off);
                LDMX4(al[mi], smb + ALO_OFS*2 + off);
            }
            #pragma unroll
            for (int p = 0; p < 2; p++) {
                uint32_t off = (uint32_t)(buf * BUF_ELEMS + (brow + p*16) * LDT + bcol) * 2;
                LDMX4(bh[p], smb + BH_OFS*2 + off);
                LDMX4(bl[p], smb + BLO_OFS*2 + off);
            }
            #pragma unroll
            for (int mi = 0; mi < 4; mi++)
                #pragma unroll
                for (int ni = 0; ni < 4; ni++) {
                    uint32_t* bhf = &bh[ni >> 1][(ni & 1) * 2];
                    uint32_t* blf = &bl[ni >> 1][(ni & 1) * 2];
                    MMA16816(acc[mi][ni], ah[mi], bhf);
                    MMA16816(acc[mi][ni], ah[mi], blf);
                    MMA16816(acc[mi][ni], al[mi], bhf);
                }
        }
        __syncthreads();
    }
}

// ---------------- qkv block body (one 128x128 tile of one of Q/K/V) --------
__device__ __forceinline__ void qkv_block(
    int qkv_id, __nv_bfloat16* sm,
    const float* __restrict__ bq, const float* __restrict__ bk,
    const float* __restrict__ bv)
{
    const int z = qkv_id >> 7;            // 0..2
    const int rem = qkv_id & 127;
    const int m0 = (rem >> 2) * 128;      // 32 m-tiles
    const int n0 = (rem & 3) * 128;       // 4 n-tiles
    const float* bias = (z == 0) ? bq : (z == 1) ? bk : bv;

    float acc[4][4][4];
    bf16x3_gemm(g_Ahi, g_Alo, g_WThi[z], g_WTlo[z], m0, n0, sm, acc);

    const int lane = threadIdx.x & 31, wid = threadIdx.x >> 5;
    const int wm = wid >> 2, wn = wid & 3;
    const int g = lane >> 2, tg = lane & 3;
    const float scale = (z == 0) ? 0.125f : 1.0f;

    __half* OUTF = (z == 0) ? g_Qf : g_Kf;

    #pragma unroll
    for (int mi = 0; mi < 4; mi++) {
        #pragma unroll
        for (int ni = 0; ni < 4; ni++) {
            int c = n0 + wn * 32 + ni * 8 + tg * 2;
            int hh = c >> 6, d = c & 63;
            float b0 = bias[c], b1 = bias[c + 1];
            #pragma unroll
            for (int half = 0; half < 2; half++) {
                int m = m0 + wm * 64 + mi * 16 + g + half * 8;
                int bb = m >> 9, n = m & 511;
                int bh = bb * NH + hh;
                float v0 = (acc[mi][ni][half*2 + 0] + b0) * scale;
                float v1 = (acc[mi][ni][half*2 + 1] + b1) * scale;
                if (z < 2) {
                    size_t a = ((size_t)bh * SEQ + n) * HD + d;
                    *(__half2*)&OUTF[a] = __floats2half2_rn(v0, v1);
                } else {
                    // V stored transposed: [b,h,d,n]
                    size_t a0 = ((size_t)bh * HD + d) * SEQ + n;
                    g_VTf[a0]       = __float2half(v0);
                    g_VTf[a0 + SEQ] = __float2half(v1);
                }
            }
        }
    }
}

// -------- dist block: smem-staged coalesced version --------
__device__ __forceinline__ void dist_block(
    int dist_id, char* smraw,
    const float* __restrict__ D, const float* __restrict__ Wd,
    const float* __restrict__ bd)
{
    float* w     = (float*)smraw;
    float* bsm   = (float*)(smraw + 2048);
    float* rows  = (float*)(smraw + 2080);
    __half* outsm = (__half*)(smraw + 71712);
    const uint32_t rows_b = sm_u32(smraw + 2080);
    const int tid = threadIdx.x;

    // stage 256 rows x 256B into smem, fully coalesced 16B chunks
    const float* src = D + (size_t)dist_id * 256 * 64;
    #pragma unroll
    for (int j = 0; j < 16; j++) {
        int c = j * 256 + tid;
        int r = c >> 4, o = c & 15;
        CP16(rows_b + (uint32_t)(r * 272 + o * 16), src + (size_t)c * 4);
    }
    CP_COMMIT();

    w[tid]       = Wd[tid];
    w[tid + 256] = Wd[tid + 256];
    if (tid < 8) bsm[tid] = bd[tid];

    CP_WAIT0();
    __syncthreads();

    // thread-per-row compute from smem (68-float stride: LDS.128 conflict-free)
    const float* rp = rows + tid * 68;
    float acc[8] = {0, 0, 0, 0, 0, 0, 0, 0};
    #pragma unroll
    for (int t = 0; t < 16; t++) {
        float4 v = *(const float4*)(rp + t * 4);
        float vv[4] = {v.x, v.y, v.z, v.w};
        #pragma unroll
        for (int e = 0; e < 4; e++) {
            int d = t * 4 + e;
            #pragma unroll
            for (int h = 0; h < 8; h++)
                acc[h] = fmaf(vv[e], w[d * 8 + h], acc[h]);
        }
    }

    // indices: 256 rows of this block share (b, q); k = k0 + tid
    int b  = dist_id >> 10;
    int rem = (dist_id * 256) & 262143;
    int q  = rem >> 9;
    int k0 = rem & 511;
    // fold key-side mask into bias (-30000 saturates softmax to 0)
    float madd = (g_maskf[b * SEQ + k0 + tid] > 0.5f) ? 0.0f : -30000.0f;
    #pragma unroll
    for (int h = 0; h < 8; h++)
        outsm[h * 256 + tid] = __float2half(acc[h] + bsm[h] + madd);
    __syncthreads();

    // coalesced global write: warp h writes its plane's 512B
    int h = tid >> 5, c = tid & 31;
    uint4 vout = *(const uint4*)&outsm[h * 256 + c * 8];
    *(uint4*)&g_biasf[(((size_t)(b * NH + h)) * SEQ + q) * SEQ + k0 + c * 8] = vout;
}

// ============== fused kernel: qkv GEMM (tensor) ∥ dist_bias (HBM) ==========
__global__ __launch_bounds__(256, 2) void fused_qkv_dist_kernel(
    const float* __restrict__ bq, const float* __restrict__ bk,
    const float* __restrict__ bv,
    const float* __restrict__ D, const float* __restrict__ Wd,
    const float* __restrict__ bd)
{
    extern __shared__ __nv_bfloat16 sm[];
    const int idx = blockIdx.x;
    const bool is_qkv = ((idx % 22) == 0) && (idx < 8448);
    if (is_qkv) {
        qkv_block(idx / 22, sm, bq, bk, bv);
    } else {
        const int nq_before = (idx < 8448) ? (idx / 22 + 1) : 384;
        dist_block(idx - nq_before, (char*)sm, D, Wd, bd);
    }
}

// ======= combined attention + output projection kernel =====================
#define AT_LD 72                      // fp16 row stride (144B, ldmatrix-safe)
#define BT_LD 72
#define OQ 0                          // Q: 128 x AT_LD = 9216 halves
#define OK 9216                       // K: [2 buf][4608]
#define OV 18432                      // V^T: [2 buf][4608]
#define OB 27648                      // bias: [2 buf][9216]
#define ATTN_SMEM_BYTES 92160

__device__ __forceinline__ void attn_load_kv(
    uint32_t smb, int buf, int kb, int tid,
    const __half* Kf, const __half* Vf, const __half* Bb)
{
    const uint32_t bo = (uint32_t)(buf * 4608 * 2);
    #pragma unroll
    for (int j = 0; j < 2; j++) {
        int ch = j * 256 + tid;
        int r = ch >> 3, cc = ch & 7;
        uint32_t so = (uint32_t)((r * AT_LD + cc * 8) * 2);
        CP16(smb + OK*2 + bo + so, Kf + (size_t)(kb * 64 + r) * HD + cc * 8);
        CP16(smb + OV*2 + bo + so, Vf + (size_t)r * SEQ + kb * 64 + cc * 8);
    }
    const uint32_t bob = (uint32_t)(buf * 9216 * 2);
    #pragma unroll
    for (int j = 0; j < 4; j++) {
        int ch = j * 256 + tid;
        int r = ch >> 3, cc = ch & 7;
        uint32_t so = (uint32_t)((r * BT_LD + cc * 8) * 2);
        CP16(smb + OB*2 + bob + so, Bb + (size_t)r * SEQ + kb * 64 + cc * 8);
    }
}

__global__ __launch_bounds__(256, 2) void attn_out_kernel(
    const float* __restrict__ bo, float* __restrict__ OUT)
{
    extern __shared__ __half smH[];
    const int tid = threadIdx.x, lane = tid & 31;

    if (blockIdx.x < 256) {
        // ================= attention path =================
        const uint32_t smb = sm_u32(smH);
        const int w = tid >> 5;
        const int idx = blockIdx.x;
        const int qb = idx & 3, h = (idx >> 2) & 7, b = idx >> 5;
        const int bh = b * NH + h;
        const int g = lane >> 2, t4 = lane & 3;

        const __half* Qf = g_Qf + ((size_t)bh * SEQ + qb * 128) * HD;
        const __half* Kf = g_Kf + (size_t)bh * SEQ * HD;
        const __half* Vf = g_VTf + (size_t)bh * HD * SEQ;
        const __half* Bb = g_biasf + ((size_t)bh * SEQ + qb * 128) * SEQ;

        #pragma unroll
        for (int j = 0; j < 4; j++) {
            int ch = j * 256 + tid;
            int r = ch >> 3, cc = ch & 7;
            uint32_t so = (uint32_t)((r * AT_LD + cc * 8) * 2);
            CP16(smb + OQ*2 + so, Qf + (size_t)r * HD + cc * 8);
        }
        attn_load_kv(smb, 0, 0, tid, Kf, Vf, Bb);
        CP_COMMIT();
        CP_WAIT0();
        __syncthreads();

        uint32_t qf[4][4];
        {
            int arow = w * 16 + (lane & 15);
            int acolb = (lane >> 4) << 3;
            #pragma unroll
            for (int ks = 0; ks < 4; ks++) {
                uint32_t off = (uint32_t)((arow * AT_LD + ks * 16 + acolb) * 2);
                LDMX4(qf[ks], smb + OQ*2 + off);
            }
        }

        float o[4][2][4];
        #pragma unroll
        for (int i = 0; i < 4; i++)
            #pragma unroll
            for (int j = 0; j < 2; j++)
                #pragma unroll
                for (int r = 0; r < 4; r++) o[i][j][r] = 0.0f;
        float lsum[2] = {0.0f, 0.0f};

        const int browc = (lane & 7) + ((lane & 16) >> 1);
        const int bcolc = lane & 8;

        for (int kb = 0; kb < 8; kb++) {
            if (kb > 0) { CP_WAIT0(); __syncthreads(); }
            if (kb + 1 < 8) {
                attn_load_kv(smb, (kb + 1) & 1, kb + 1, tid, Kf, Vf, Bb);
                CP_COMMIT();
            }
            const uint32_t bufo  = (uint32_t)((kb & 1) * 4608 * 2);
            const int      bbase = OB + (kb & 1) * 9216;

            // ---- P = exp(Q K^T + bias+mask); no max, no correction ----
            float sv[2][16];
            #pragma unroll
            for (int ni2 = 0; ni2 < 4; ni2++) {
                float s0[4] = {0, 0, 0, 0}, s1[4] = {0, 0, 0, 0};
                #pragma unroll
                for (int ks = 0; ks < 4; ks++) {
                    uint32_t off = (uint32_t)(((ni2 * 16 + browc) * AT_LD + ks * 16 + bcolc) * 2);
                    uint32_t kf4[4];
                    LDMX4(kf4, smb + OK*2 + bufo + off);
                    MMA16816H(s0, qf[ks], &kf4[0]);
                    MMA16816H(s1, qf[ks], &kf4[2]);
                }
                #pragma unroll
                for (int n8p = 0; n8p < 2; n8p++) {
                    const float* sp = n8p ? s1 : s0;
                    int lcol = ni2 * 16 + n8p * 8 + t4 * 2;
                    #pragma unroll
                    for (int rh = 0; rh < 2; rh++) {
                        __half2 bb = *(const __half2*)
                            &smH[bbase + (w * 16 + g + rh * 8) * BT_LD + lcol];
                        float2 bf = __half22float2(bb);
                        float p0 = __expf(sp[rh*2 + 0] + bf.x);
                        float p1 = __expf(sp[rh*2 + 1] + bf.y);
                        sv[rh][ni2*4 + n8p*2 + 0] = p0;
                        sv[rh][ni2*4 + n8p*2 + 1] = p1;
                        lsum[rh] += p0 + p1;
                    }
                }
            }

            // ---- O += P V ----
            #pragma unroll
            for (int ks = 0; ks < 4; ks++) {
                uint32_t pf[4];
                pf[0] = packh2(sv[0][ks*4 + 0], sv[0][ks*4 + 1]);
                pf[1] = packh2(sv[1][ks*4 + 0], sv[1][ks*4 + 1]);
                pf[2] = packh2(sv[0][ks*4 + 2], sv[0][ks*4 + 3]);
                pf[3] = packh2(sv[1][ks*4 + 2], sv[1][ks*4 + 3]);
                #pragma unroll
                for (int ni2 = 0; ni2 < 4; ni2++) {
                    uint32_t off = (uint32_t)(((ni2 * 16 + browc) * AT_LD + ks * 16 + bcolc) * 2);
                    uint32_t vf4[4];
                    LDMX4(vf4, smb + OV*2 + bufo + off);
                    MMA16816H(o[ni2][0], pf, &vf4[0]);
                    MMA16816H(o[ni2][1], pf, &vf4[2]);
                }
            }
        }

        // ---- row sums + epilogue ----
        #pragma unroll
        for (int rh = 0; rh < 2; rh++) {
            lsum[rh] += __shfl_xor_sync(0xffffffffu, lsum[rh], 1);
            lsum[rh] += __shfl_xor_sync(0xffffffffu, lsum[rh], 2);
        }
        float inv[2] = {1.0f / lsum[0], 1.0f / lsum[1]};
        #pragma unroll
        for (int ni2 = 0; ni2 < 4; ni2++) {
            #pragma unroll
            for (int n8p = 0; n8p < 2; n8p++) {
                int col = h * 64 + ni2 * 16 + n8p * 8 + t4 * 2;
                #pragma unroll
                for (int rh = 0; rh < 2; rh++) {
                    size_t m = (size_t)b * SEQ + qb * 128 + w * 16 + g + rh * 8;
                    float v0 = o[ni2][n8p][rh*2 + 0] * inv[rh];
                    float v1 = o[ni2][n8p][rh*2 + 1] * inv[rh];
                    uint32_t hiw, low;
                    split2(v0, v1, hiw, low);
                    *(uint32_t*)&g_Ahi[m * HID + col] = hiw;
                    *(uint32_t*)&g_Alo[m * HID + col] = low;
                }
            }
        }

        // signal: this head's ctx rows for (b,qb) are done
        __syncthreads();
        if (tid == 0) {
            __threadfence();
            atomicAdd(&g_ready[(b << 2) | qb], 1);
        }
    } else {
        // ================= output projection path =================
        const int oi = blockIdx.x - 256;       // 0..127
        const int mt = oi >> 2;                // 0..31 = (b,qb) tile
        const int n0 = (oi & 3) * 128;
        const int m0 = mt * 128;

        // wait until all 8 head-CTAs of this (b,qb) tile have written ctx
        if (tid == 0) {
            while (atomicAdd(&g_ready[mt], 0) < 8) __nanosleep(128);
        }
        __syncthreads();

        float acc[4][4][4];
        bf16x3_gemm(g_Ahi, g_Alo, g_WThi[3], g_WTlo[3], m0, n0,
                    (__nv_bfloat16*)smH, acc);

        const int wid = tid >> 5;
        const int wm = wid >> 2, wn = wid & 3;
        const int g = lane >> 2, tg = lane & 3;

        #pragma unroll
        for (int mi = 0; mi < 4; mi++) {
            #pragma unroll
            for (int ni = 0; ni < 4; ni++) {
                int c = n0 + wn * 32 + ni * 8 + tg * 2;
                float b0 = bo[c], b1 = bo[c + 1];
                #pragma unroll
                for (int half = 0; half < 2; half++) {
                    int m = m0 + wm * 64 + mi * 16 + g + half * 8;
                    float mf = g_maskf[m];
                    float2 v;
                    v.x = (mf > 0.5f) ? acc[mi][ni][half*2 + 0] + b0 : 0.0f;
                    v.y = (mf > 0.5f) ? acc[mi][ni][half*2 + 1] + b1 : 0.0f;
                    *(float2*)&OUT[(size_t)m * HID + c] = v;
                }
            }
        }
    }
}

// ---------------- launch ----------------
extern "C" void kernel_launch(void* const* d_in, const int* in_sizes, int n_in,
                              void* d_out, int out_size)
{
    const float* x    = (const float*)d_in[0];
    const float* dist = (const float*)d_in[1];
    const unsigned char* mask = (const unsigned char*)d_in[2];
    const float* Wq = (const float*)d_in[3];
    const float* bq = (const float*)d_in[4];
    const float* Wk = (const float*)d_in[5];
    const float* bk = (const float*)d_in[6];
    const float* Wv = (const float*)d_in[7];
    const float* bv = (const float*)d_in[8];
    const float* Wo = (const float*)d_in[9];
    const float* bo = (const float*)d_in[10];
    const float* Wd = (const float*)d_in[11];
    const float* bd = (const float*)d_in[12];
    float* out = (float*)d_out;

    cudaFuncSetAttribute(fused_qkv_dist_kernel, cudaFuncAttributeMaxDynamicSharedMemorySize,
                         GEMM_SMEM_BYTES);
    cudaFuncSetAttribute(attn_out_kernel, cudaFuncAttributeMaxDynamicSharedMemorySize,
                         ATTN_SMEM_BYTES);

    prep_x_kernel<<<2048, 256>>>(x);
    prep_w_kernel<<<1025, 256>>>(Wq, Wk, Wv, Wo, mask);
    fused_qkv_dist_kernel<<<8576, 256, GEMM_SMEM_BYTES>>>(bq, bk, bv, dist, Wd, bd);
    attn_out_kernel<<<384, 256, ATTN_SMEM_BYTES>>>(bo, out);
}

// round 13
// speedup vs baseline: 1.1745x; 1.1745x over previous
#include <cuda_runtime.h>
#include <cuda_bf16.h>
#include <cuda_fp16.h>
#include <stdint.h>
#include <math.h>

#define NB 8
#define NH 8
#define SEQ 512
#define HID 512
#define HD 64

// ---------------- scratch (device globals; no allocations) ----------------
__device__ float g_maskf[NB*SEQ];                        // 0/1 floats
__device__ __half g_biasf[(size_t)NB*NH*SEQ*SEQ];        // 32 MB fp16 bias (+key mask)
__device__ __half g_Qf[NB*NH*SEQ*HD];                    // [b,h,n,d] (pre-scaled)
__device__ __half g_Kf[NB*NH*SEQ*HD];                    // [b,h,n,d]
__device__ __half g_VTf[NB*NH*SEQ*HD];                   // [b,h,d,n]
__device__ __nv_bfloat16 g_Ahi[NB*SEQ*HID], g_Alo[NB*SEQ*HID];   // x / ctx
__device__ __nv_bfloat16 g_WThi[4][HID*HID], g_WTlo[4][HID*HID]; // W^T [n][k]

// ---------------- PTX helpers ----------------
__device__ __forceinline__ uint32_t sm_u32(const void* p) {
    return (uint32_t)__cvta_generic_to_shared(p);
}
#define CP16(dst_u32, gptr) \
    asm volatile("cp.async.ca.shared.global [%0], [%1], 16;" :: "r"(dst_u32), "l"(gptr))
#define CP_COMMIT() asm volatile("cp.async.commit_group;")
#define CP_WAIT0()  asm volatile("cp.async.wait_group 0;")
#define LDMX4(r, addr) \
    asm volatile("ldmatrix.sync.aligned.m8n8.x4.shared.b16 {%0,%1,%2,%3}, [%4];" \
        : "=r"((r)[0]), "=r"((r)[1]), "=r"((r)[2]), "=r"((r)[3]) : "r"(addr))
#define MMA16816(d, a, b) \
    asm volatile("mma.sync.aligned.m16n8k16.row.col.f32.bf16.bf16.f32 " \
        "{%0,%1,%2,%3},{%4,%5,%6,%7},{%8,%9},{%0,%1,%2,%3};\n" \
        : "+f"((d)[0]), "+f"((d)[1]), "+f"((d)[2]), "+f"((d)[3]) \
        : "r"((a)[0]), "r"((a)[1]), "r"((a)[2]), "r"((a)[3]), "r"((b)[0]), "r"((b)[1]))
#define MMA16816H(d, a, b) \
    asm volatile("mma.sync.aligned.m16n8k16.row.col.f32.f16.f16.f32 " \
        "{%0,%1,%2,%3},{%4,%5,%6,%7},{%8,%9},{%0,%1,%2,%3};\n" \
        : "+f"((d)[0]), "+f"((d)[1]), "+f"((d)[2]), "+f"((d)[3]) \
        : "r"((a)[0]), "r"((a)[1]), "r"((a)[2]), "r"((a)[3]), "r"((b)[0]), "r"((b)[1]))

// split pair (a=elem0, b=elem1) into packed bf16x2 hi and lo residual
__device__ __forceinline__ void split2(float a, float b, uint32_t& hi, uint32_t& lo) {
    __nv_bfloat16 ha = __float2bfloat16(a), hb = __float2bfloat16(b);
    __nv_bfloat16 la = __float2bfloat16(a - __bfloat162float(ha));
    __nv_bfloat16 lb = __float2bfloat16(b - __bfloat162float(hb));
    hi = ((uint32_t)__bfloat16_as_ushort(hb) << 16) | (uint32_t)__bfloat16_as_ushort(ha);
    lo = ((uint32_t)__bfloat16_as_ushort(lb) << 16) | (uint32_t)__bfloat16_as_ushort(la);
}

__device__ __forceinline__ uint32_t packh2(float a, float b) {
    __half2 h = __floats2half2_rn(a, b);
    return *reinterpret_cast<uint32_t*>(&h);
}

// ================= prep_x: x -> hi/lo bf16 split ==============
__global__ __launch_bounds__(256) void prep_x_kernel(const float* __restrict__ x) {
    int i = blockIdx.x * 256 + threadIdx.x;     // over float4s (2M floats)
    float4 v = ((const float4*)x)[i];
    uint32_t h0, l0, h1, l1;
    split2(v.x, v.y, h0, l0);
    split2(v.z, v.w, h1, l1);
    uint32_t* hp = (uint32_t*)(g_Ahi + 4*(size_t)i);
    uint32_t* lp = (uint32_t*)(g_Alo + 4*(size_t)i);
    hp[0] = h0; hp[1] = h1;
    lp[0] = l0; lp[1] = l1;
}

// ================= prep_w: W^T hi/lo + mask ==========
__global__ __launch_bounds__(256) void prep_w_kernel(
    const float* __restrict__ Wq, const float* __restrict__ Wk,
    const float* __restrict__ Wv, const float* __restrict__ Wo,
    const unsigned char* __restrict__ raw)
{
    __shared__ float t[32][33];
    __shared__ int mode;
    const int bx = blockIdx.x;
    const int tid = threadIdx.x;

    if (bx < 1024) {
        // ---- W -> W^T hi/lo (32x32 tile transpose) ----
        const int z = bx >> 8;
        const int bxx = bx & 15, byy = (bx >> 4) & 15;
        const float* W = (z == 0) ? Wq : (z == 1) ? Wk : (z == 2) ? Wv : Wo;
        __nv_bfloat16* Th = g_WThi[z];
        __nv_bfloat16* Tl = g_WTlo[z];
        int tx = tid & 31, ty = tid >> 5;       // 32 x 8
        int n0 = bxx * 32, k0 = byy * 32;
        #pragma unroll
        for (int j = 0; j < 4; j++)
            t[ty + 8*j][tx] = W[(size_t)(k0 + ty + 8*j) * HID + n0 + tx];
        __syncthreads();
        #pragma unroll
        for (int j = 0; j < 4; j++) {
            float v = t[tx][ty + 8*j];
            __nv_bfloat16 h = __float2bfloat16(v);
            __nv_bfloat16 l = __float2bfloat16(v - __bfloat162float(h));
            size_t o = (size_t)(n0 + ty + 8*j) * HID + k0 + tx;
            Th[o] = h;
            Tl[o] = l;
        }
    } else {
        // ---- mask normalization (dtype-agnostic) ----
        if (tid == 0) {
            const unsigned int* w = (const unsigned int*)raw;
            int cf = 0, byteish = 0;
            for (int i = 0; i < 128; i++) {
                unsigned int v = w[i];
                if (v == 0x3F800000u) cf++;
                bool b01 = true;
                #pragma unroll
                for (int bb = 0; bb < 4; bb++) {
                    unsigned int by = (v >> (8*bb)) & 0xFFu;
                    if (by > 1u) b01 = false;
                }
                if (b01 && v > 1u) byteish++;
            }
            mode = (cf > 64) ? 0 : ((byteish > 0) ? 2 : 1);  // 0=f32, 1=i32, 2=u8
        }
        __syncthreads();
        int md = mode;
        for (int i = tid; i < NB*SEQ; i += 256) {
            float m;
            if (md == 0)      m = (((const float*)raw)[i] != 0.0f) ? 1.0f : 0.0f;
            else if (md == 1) m = (((const int*)raw)[i]   != 0)    ? 1.0f : 0.0f;
            else              m = (raw[i]                 != 0)    ? 1.0f : 0.0f;
            g_maskf[i] = m;
        }
    }
}

// ================= bf16x3 tensor-core GEMM core (verified R4) =============
#define GBK 32
#define LDT 40
#define BUF_ELEMS (128 * LDT)
#define AH_OFS 0
#define ALO_OFS (2 * BUF_ELEMS)
#define BH_OFS  (4 * BUF_ELEMS)
#define BLO_OFS (6 * BUF_ELEMS)
#define GEMM_SMEM_BYTES (8 * BUF_ELEMS * 2)

__device__ __forceinline__ void bf16x3_gemm(
    const __nv_bfloat16* __restrict__ Ahi, const __nv_bfloat16* __restrict__ Alo,
    const __nv_bfloat16* __restrict__ Bhi, const __nv_bfloat16* __restrict__ Blo,
    int m0, int n0, __nv_bfloat16* sm, float acc[4][4][4])
{
    const int tid = threadIdx.x;
    const int lane = tid & 31, wid = tid >> 5;
    const int wm = wid >> 2, wn = wid & 3;
    const uint32_t smb = sm_u32(sm);

    #pragma unroll
    for (int mi = 0; mi < 4; mi++)
        #pragma unroll
        for (int ni = 0; ni < 4; ni++)
            #pragma unroll
            for (int r = 0; r < 4; r++) acc[mi][ni][r] = 0.0f;

    const int c0 = tid, c1 = tid + 256;
    const int r0 = c0 >> 2, s0 = c0 & 3;
    const int r1 = c1 >> 2, s1 = c1 & 3;

    auto load_chunk = [&](int kc, int buf) {
        const int k0 = kc * GBK;
        const uint32_t so0 = (uint32_t)(buf * BUF_ELEMS + r0 * LDT + s0 * 8) * 2;
        const uint32_t so1 = (uint32_t)(buf * BUF_ELEMS + r1 * LDT + s1 * 8) * 2;
        const size_t ga0 = (size_t)(m0 + r0) * HID + k0 + s0 * 8;
        const size_t ga1 = (size_t)(m0 + r1) * HID + k0 + s1 * 8;
        const size_t gb0 = (size_t)(n0 + r0) * HID + k0 + s0 * 8;
        const size_t gb1 = (size_t)(n0 + r1) * HID + k0 + s1 * 8;
        CP16(smb + AH_OFS*2  + so0, Ahi + ga0);
        CP16(smb + AH_OFS*2  + so1, Ahi + ga1);
        CP16(smb + ALO_OFS*2 + so0, Alo + ga0);
        CP16(smb + ALO_OFS*2 + so1, Alo + ga1);
        CP16(smb + BH_OFS*2  + so0, Bhi + gb0);
        CP16(smb + BH_OFS*2  + so1, Bhi + gb1);
        CP16(smb + BLO_OFS*2 + so0, Blo + gb0);
        CP16(smb + BLO_OFS*2 + so1, Blo + gb1);
    };

    const int arow = wm * 64 + (lane & 15);
    const int acolb = (lane >> 4) << 3;
    const int brow = wn * 32 + (lane & 7) + ((lane & 16) >> 1);
    const int bcolb = lane & 8;

    load_chunk(0, 0);
    CP_COMMIT();

    for (int kc = 0; kc < HID / GBK; kc++) {
        CP_WAIT0();
        __syncthreads();
        if (kc + 1 < HID / GBK) {
            load_chunk(kc + 1, (kc + 1) & 1);
            CP_COMMIT();
        }
        const int buf = kc & 1;
        #pragma unroll
        for (int ks = 0; ks < 2; ks++) {
            uint32_t ah[4][4], al[4][4], bh[2][4], bl[2][4];
            const int acol = ks * 16 + acolb;
            const int bcol = ks * 16 + bcolb;
            #pragma unroll
            for (int mi = 0; mi < 4; mi++) {
                uint32_t off = (uint32_t)(buf * BUF_ELEMS + (arow + mi*16) * LDT + acol) * 2;
                LDMX4(ah[mi], smb + AH_OFS*2 + off);
                LDMX4(al[mi], smb + ALO_OFS*2 + off);
            }
            #pragma unroll
            for (int p = 0; p < 2; p++) {
                uint32_t off = (uint32_t)(buf * BUF_ELEMS + (brow + p*16) * LDT + bcol) * 2;
                LDMX4(bh[p], smb + BH_OFS*2 + off);
                LDMX4(bl[p], smb + BLO_OFS*2 + off);
            }
            #pragma unroll
            for (int mi = 0; mi < 4; mi++)
                #pragma unroll
                for (int ni = 0; ni < 4; ni++) {
                    uint32_t* bhf = &bh[ni >> 1][(ni & 1) * 2];
                    uint32_t* blf = &bl[ni >> 1][(ni & 1) * 2];
                    MMA16816(acc[mi][ni], ah[mi], bhf);
                    MMA16816(acc[mi][ni], ah[mi], blf);
                    MMA16816(acc[mi][ni], al[mi], bhf);
                }
        }
        __syncthreads();
    }
}

// ---------------- qkv block body (one 128x128 tile of one of Q/K/V) --------
__device__ __forceinline__ void qkv_block(
    int qkv_id, __nv_bfloat16* sm,
    const float* __restrict__ bq, const float* __restrict__ bk,
    const float* __restrict__ bv)
{
    const int z = qkv_id >> 7;            // 0..2
    const int rem = qkv_id & 127;
    const int m0 = (rem >> 2) * 128;      // 32 m-tiles
    const int n0 = (rem & 3) * 128;       // 4 n-tiles
    const float* bias = (z == 0) ? bq : (z == 1) ? bk : bv;

    float acc[4][4][4];
    bf16x3_gemm(g_Ahi, g_Alo, g_WThi[z], g_WTlo[z], m0, n0, sm, acc);

    const int lane = threadIdx.x & 31, wid = threadIdx.x >> 5;
    const int wm = wid >> 2, wn = wid & 3;
    const int g = lane >> 2, tg = lane & 3;
    const float scale = (z == 0) ? 0.125f : 1.0f;

    __half* OUTF = (z == 0) ? g_Qf : g_Kf;

    #pragma unroll
    for (int mi = 0; mi < 4; mi++) {
        #pragma unroll
        for (int ni = 0; ni < 4; ni++) {
            int c = n0 + wn * 32 + ni * 8 + tg * 2;
            int hh = c >> 6, d = c & 63;
            float b0 = bias[c], b1 = bias[c + 1];
            #pragma unroll
            for (int half = 0; half < 2; half++) {
                int m = m0 + wm * 64 + mi * 16 + g + half * 8;
                int bb = m >> 9, n = m & 511;
                int bh = bb * NH + hh;
                float v0 = (acc[mi][ni][half*2 + 0] + b0) * scale;
                float v1 = (acc[mi][ni][half*2 + 1] + b1) * scale;
                if (z < 2) {
                    size_t a = ((size_t)bh * SEQ + n) * HD + d;
                    *(__half2*)&OUTF[a] = __floats2half2_rn(v0, v1);
                } else {
                    // V stored transposed: [b,h,d,n]
                    size_t a0 = ((size_t)bh * HD + d) * SEQ + n;
                    g_VTf[a0]       = __float2half(v0);
                    g_VTf[a0 + SEQ] = __float2half(v1);
                }
            }
        }
    }
}

// -------- dist block: smem-staged coalesced version --------
__device__ __forceinline__ void dist_block(
    int dist_id, char* smraw,
    const float* __restrict__ D, const float* __restrict__ Wd,
    const float* __restrict__ bd)
{
    float* w     = (float*)smraw;
    float* bsm   = (float*)(smraw + 2048);
    float* rows  = (float*)(smraw + 2080);
    __half* outsm = (__half*)(smraw + 71712);
    const uint32_t rows_b = sm_u32(smraw + 2080);
    const int tid = threadIdx.x;

    // stage 256 rows x 256B into smem, fully coalesced 16B chunks
    const float* src = D + (size_t)dist_id * 256 * 64;
    #pragma unroll
    for (int j = 0; j < 16; j++) {
        int c = j * 256 + tid;
        int r = c >> 4, o = c & 15;
        CP16(rows_b + (uint32_t)(r * 272 + o * 16), src + (size_t)c * 4);
    }
    CP_COMMIT();

    w[tid]       = Wd[tid];
    w[tid + 256] = Wd[tid + 256];
    if (tid < 8) bsm[tid] = bd[tid];

    CP_WAIT0();
    __syncthreads();

    // thread-per-row compute from smem (68-float stride: LDS.128 conflict-free)
    const float* rp = rows + tid * 68;
    float acc[8] = {0, 0, 0, 0, 0, 0, 0, 0};
    #pragma unroll
    for (int t = 0; t < 16; t++) {
        float4 v = *(const float4*)(rp + t * 4);
        float vv[4] = {v.x, v.y, v.z, v.w};
        #pragma unroll
        for (int e = 0; e < 4; e++) {
            int d = t * 4 + e;
            #pragma unroll
            for (int h = 0; h < 8; h++)
                acc[h] = fmaf(vv[e], w[d * 8 + h], acc[h]);
        }
    }

    // indices: 256 rows of this block share (b, q); k = k0 + tid
    int b  = dist_id >> 10;
    int rem = (dist_id * 256) & 262143;
    int q  = rem >> 9;
    int k0 = rem & 511;
    // fold key-side mask into bias (-30000 saturates softmax to 0)
    float madd = (g_maskf[b * SEQ + k0 + tid] > 0.5f) ? 0.0f : -30000.0f;
    #pragma unroll
    for (int h = 0; h < 8; h++)
        outsm[h * 256 + tid] = __float2half(acc[h] + bsm[h] + madd);
    __syncthreads();

    // coalesced global write: warp h writes its plane's 512B
    int h = tid >> 5, c = tid & 31;
    uint4 vout = *(const uint4*)&outsm[h * 256 + c * 8];
    *(uint4*)&g_biasf[(((size_t)(b * NH + h)) * SEQ + q) * SEQ + k0 + c * 8] = vout;
}

// ============== fused kernel: qkv GEMM (tensor) ∥ dist_bias (HBM) ==========
// interleave qkv every 14 indices: last qkv CTA starts ~63% into the
// schedule so its ~53us runtime finishes with the dist stream (kills tail).
__global__ __launch_bounds__(256, 2) void fused_qkv_dist_kernel(
    const float* __restrict__ bq, const float* __restrict__ bk,
    const float* __restrict__ bv,
    const float* __restrict__ D, const float* __restrict__ Wd,
    const float* __restrict__ bd)
{
    extern __shared__ __nv_bfloat16 sm[];
    const int idx = blockIdx.x;
    const bool is_qkv = ((idx % 14) == 0) && (idx < 5376);
    if (is_qkv) {
        qkv_block(idx / 14, sm, bq, bk, bv);
    } else {
        const int nq_before = (idx < 5376) ? (idx / 14 + 1) : 384;
        dist_block(idx - nq_before, (char*)sm, D, Wd, bd);
    }
}

// ---------------- output projection (reads ctx hi/lo written by attn) ------
__global__ __launch_bounds__(256) void gemm_out_kernel(
    const float* __restrict__ bo, float* __restrict__ OUT)
{
    extern __shared__ __nv_bfloat16 sm[];
    const int m0 = blockIdx.y * 128, n0 = blockIdx.x * 128;

    float acc[4][4][4];
    bf16x3_gemm(g_Ahi, g_Alo, g_WThi[3], g_WTlo[3], m0, n0, sm, acc);

    const int lane = threadIdx.x & 31, wid = threadIdx.x >> 5;
    const int wm = wid >> 2, wn = wid & 3;
    const int g = lane >> 2, tg = lane & 3;

    #pragma unroll
    for (int mi = 0; mi < 4; mi++) {
        #pragma unroll
        for (int ni = 0; ni < 4; ni++) {
            int c = n0 + wn * 32 + ni * 8 + tg * 2;
            float b0 = bo[c], b1 = bo[c + 1];
            #pragma unroll
            for (int half = 0; half < 2; half++) {
                int m = m0 + wm * 64 + mi * 16 + g + half * 8;
                float mf = g_maskf[m];
                float2 v;
                v.x = (mf > 0.5f) ? acc[mi][ni][half*2 + 0] + b0 : 0.0f;
                v.y = (mf > 0.5f) ? acc[mi][ni][half*2 + 1] + b1 : 0.0f;
                *(float2*)&OUT[(size_t)m * HID + c] = v;
            }
        }
    }
}

// ======= fp16 tensor-core flash attention, exact softmax w/o running max ===
#define AT_LD 72                      // fp16 row stride (144B, ldmatrix-safe)
#define BT_LD 72
#define OQ 0                          // Q: 128 x AT_LD = 9216 halves
#define OK 9216                       // K: [2 buf][4608]
#define OV 18432                      // V^T: [2 buf][4608]
#define OB 27648                      // bias: [2 buf][9216]
#define ATTN_SMEM_BYTES 92160

__device__ __forceinline__ void attn_load_kv(
    uint32_t smb, int buf, int kb, int tid,
    const __half* Kf, const __half* Vf, const __half* Bb)
{
    const uint32_t bo = (uint32_t)(buf * 4608 * 2);
    #pragma unroll
    for (int j = 0; j < 2; j++) {
        int ch = j * 256 + tid;
        int r = ch >> 3, cc = ch & 7;
        uint32_t so = (uint32_t)((r * AT_LD + cc * 8) * 2);
        CP16(smb + OK*2 + bo + so, Kf + (size_t)(kb * 64 + r) * HD + cc * 8);
        CP16(smb + OV*2 + bo + so, Vf + (size_t)r * SEQ + kb * 64 + cc * 8);
    }
    const uint32_t bob = (uint32_t)(buf * 9216 * 2);
    #pragma unroll
    for (int j = 0; j < 4; j++) {
        int ch = j * 256 + tid;
        int r = ch >> 3, cc = ch & 7;
        uint32_t so = (uint32_t)((r * BT_LD + cc * 8) * 2);
        CP16(smb + OB*2 + bob + so, Bb + (size_t)r * SEQ + kb * 64 + cc * 8);
    }
}

__global__ __launch_bounds__(256, 2) void attn_mma_kernel() {
    extern __shared__ __half smH[];
    const uint32_t smb = sm_u32(smH);
    const int tid = threadIdx.x, lane = tid & 31, w = tid >> 5;   // 8 warps
    const int qb = blockIdx.x, h = blockIdx.y, b = blockIdx.z;
    const int bh = b * NH + h;
    const int g = lane >> 2, t4 = lane & 3;

    const __half* Qf = g_Qf + ((size_t)bh * SEQ + qb * 128) * HD;
    const __half* Kf = g_Kf + (size_t)bh * SEQ * HD;
    const __half* Vf = g_VTf + (size_t)bh * HD * SEQ;
    const __half* Bb = g_biasf + ((size_t)bh * SEQ + qb * 128) * SEQ;

    // Q tile (128 x 64) + first KV+bias tiles
    #pragma unroll
    for (int j = 0; j < 4; j++) {
        int ch = j * 256 + tid;
        int r = ch >> 3, cc = ch & 7;
        uint32_t so = (uint32_t)((r * AT_LD + cc * 8) * 2);
        CP16(smb + OQ*2 + so, Qf + (size_t)r * HD + cc * 8);
    }
    attn_load_kv(smb, 0, 0, tid, Kf, Vf, Bb);
    CP_COMMIT();
    CP_WAIT0();
    __syncthreads();

    // Q fragments; warp w owns rows [w*16, w*16+16)
    uint32_t qf[4][4];
    {
        int arow = w * 16 + (lane & 15);
        int acolb = (lane >> 4) << 3;
        #pragma unroll
        for (int ks = 0; ks < 4; ks++) {
            uint32_t off = (uint32_t)((arow * AT_LD + ks * 16 + acolb) * 2);
            LDMX4(qf[ks], smb + OQ*2 + off);
        }
    }

    float o[4][2][4];
    #pragma unroll
    for (int i = 0; i < 4; i++)
        #pragma unroll
        for (int j = 0; j < 2; j++)
            #pragma unroll
            for (int r = 0; r < 4; r++) o[i][j][r] = 0.0f;
    float lsum[2] = {0.0f, 0.0f};          // per-thread partial row sums

    const int browc = (lane & 7) + ((lane & 16) >> 1);
    const int bcolc = lane & 8;

    for (int kb = 0; kb < 8; kb++) {
        if (kb > 0) { CP_WAIT0(); __syncthreads(); }
        if (kb + 1 < 8) {
            attn_load_kv(smb, (kb + 1) & 1, kb + 1, tid, Kf, Vf, Bb);
            CP_COMMIT();
        }
        const uint32_t bufo  = (uint32_t)((kb & 1) * 4608 * 2);
        const int      bbase = OB + (kb & 1) * 9216;

        // ---- P = exp(Q K^T + bias+mask) directly; no max, no correction ----
        float sv[2][16];
        #pragma unroll
        for (int ni2 = 0; ni2 < 4; ni2++) {
            float s0[4] = {0, 0, 0, 0}, s1[4] = {0, 0, 0, 0};
            #pragma unroll
            for (int ks = 0; ks < 4; ks++) {
                uint32_t off = (uint32_t)(((ni2 * 16 + browc) * AT_LD + ks * 16 + bcolc) * 2);
                uint32_t kf4[4];
                LDMX4(kf4, smb + OK*2 + bufo + off);
                MMA16816H(s0, qf[ks], &kf4[0]);
                MMA16816H(s1, qf[ks], &kf4[2]);
            }
            #pragma unroll
            for (int n8p = 0; n8p < 2; n8p++) {
                const float* sp = n8p ? s1 : s0;
                int lcol = ni2 * 16 + n8p * 8 + t4 * 2;
                #pragma unroll
                for (int rh = 0; rh < 2; rh++) {
                    __half2 bb = *(const __half2*)
                        &smH[bbase + (w * 16 + g + rh * 8) * BT_LD + lcol];
                    float2 bf = __half22float2(bb);
                    float p0 = __expf(sp[rh*2 + 0] + bf.x);
                    float p1 = __expf(sp[rh*2 + 1] + bf.y);
                    sv[rh][ni2*4 + n8p*2 + 0] = p0;
                    sv[rh][ni2*4 + n8p*2 + 1] = p1;
                    lsum[rh] += p0 + p1;
                }
            }
        }

        // ---- O += P V (fp16 single pass) ----
        #pragma unroll
        for (int ks = 0; ks < 4; ks++) {
            uint32_t pf[4];
            pf[0] = packh2(sv[0][ks*4 + 0], sv[0][ks*4 + 1]);
            pf[1] = packh2(sv[1][ks*4 + 0], sv[1][ks*4 + 1]);
            pf[2] = packh2(sv[0][ks*4 + 2], sv[0][ks*4 + 3]);
            pf[3] = packh2(sv[1][ks*4 + 2], sv[1][ks*4 + 3]);
            #pragma unroll
            for (int ni2 = 0; ni2 < 4; ni2++) {
                uint32_t off = (uint32_t)(((ni2 * 16 + browc) * AT_LD + ks * 16 + bcolc) * 2);
                uint32_t vf4[4];
                LDMX4(vf4, smb + OV*2 + bufo + off);
                MMA16816H(o[ni2][0], pf, &vf4[0]);
                MMA16816H(o[ni2][1], pf, &vf4[2]);
            }
        }
    }

    // ---- final row-sum reduction (once) + epilogue ----
    #pragma unroll
    for (int rh = 0; rh < 2; rh++) {
        lsum[rh] += __shfl_xor_sync(0xffffffffu, lsum[rh], 1);
        lsum[rh] += __shfl_xor_sync(0xffffffffu, lsum[rh], 2);
    }
    float inv[2] = {1.0f / lsum[0], 1.0f / lsum[1]};
    #pragma unroll
    for (int ni2 = 0; ni2 < 4; ni2++) {
        #pragma unroll
        for (int n8p = 0; n8p < 2; n8p++) {
            int col = h * 64 + ni2 * 16 + n8p * 8 + t4 * 2;
            #pragma unroll
            for (int rh = 0; rh < 2; rh++) {
                size_t m = (size_t)b * SEQ + qb * 128 + w * 16 + g + rh * 8;
                float v0 = o[ni2][n8p][rh*2 + 0] * inv[rh];
                float v1 = o[ni2][n8p][rh*2 + 1] * inv[rh];
                uint32_t hiw, low;
                split2(v0, v1, hiw, low);
                *(uint32_t*)&g_Ahi[m * HID + col] = hiw;
                *(uint32_t*)&g_Alo[m * HID + col] = low;
            }
        }
    }
}

// ---------------- launch ----------------
extern "C" void kernel_launch(void* const* d_in, const int* in_sizes, int n_in,
                              void* d_out, int out_size)
{
    const float* x    = (const float*)d_in[0];
    const float* dist = (const float*)d_in[1];
    const unsigned char* mask = (const unsigned char*)d_in[2];
    const float* Wq = (const float*)d_in[3];
    const float* bq = (const float*)d_in[4];
    const float* Wk = (const float*)d_in[5];
    const float* bk = (const float*)d_in[6];
    const float* Wv = (const float*)d_in[7];
    const float* bv = (const float*)d_in[8];
    const float* Wo = (const float*)d_in[9];
    const float* bo = (const float*)d_in[10];
    const float* Wd = (const float*)d_in[11];
    const float* bd = (const float*)d_in[12];
    float* out = (float*)d_out;

    cudaFuncSetAttribute(fused_qkv_dist_kernel, cudaFuncAttributeMaxDynamicSharedMemorySize,
                         GEMM_SMEM_BYTES);
    cudaFuncSetAttribute(gemm_out_kernel, cudaFuncAttributeMaxDynamicSharedMemorySize,
                         GEMM_SMEM_BYTES);
    cudaFuncSetAttribute(attn_mma_kernel, cudaFuncAttributeMaxDynamicSharedMemorySize,
                         ATTN_SMEM_BYTES);

    prep_x_kernel<<<2048, 256>>>(x);
    prep_w_kernel<<<1025, 256>>>(Wq, Wk, Wv, Wo, mask);
    fused_qkv_dist_kernel<<<8576, 256, GEMM_SMEM_BYTES>>>(bq, bk, bv, dist, Wd, bd);
    attn_mma_kernel<<<dim3(4, NH, NB), 256, ATTN_SMEM_BYTES>>>();
    gemm_out_kernel<<<dim3(4, 32), 256, GEMM_SMEM_BYTES>>>(bo, out);
}

// round 14
// speedup vs baseline: 1.2005x; 1.0221x over previous
#include <cuda_runtime.h>
#include <cuda_bf16.h>
#include <cuda_fp16.h>
#include <stdint.h>
#include <math.h>

#define NB 8
#define NH 8
#define SEQ 512
#define HID 512
#define HD 64

// ---------------- scratch (device globals; no allocations) ----------------
__device__ float g_maskf[NB*SEQ];                        // 0/1 floats
__device__ __half g_biasf[(size_t)NB*NH*SEQ*SEQ];        // 32 MB fp16 bias (+key mask)
__device__ __half g_Qf[NB*NH*SEQ*HD];                    // [b,h,n,d] (pre-scaled)
__device__ __half g_Kf[NB*NH*SEQ*HD];                    // [b,h,n,d]
__device__ __half g_VTf[NB*NH*SEQ*HD];                   // [b,h,d,n]
__device__ __nv_bfloat16 g_Ahi[NB*SEQ*HID], g_Alo[NB*SEQ*HID];   // x / ctx
__device__ __nv_bfloat16 g_WThi[4][HID*HID], g_WTlo[4][HID*HID]; // W^T [n][k]

// ---------------- PTX helpers ----------------
__device__ __forceinline__ uint32_t sm_u32(const void* p) {
    return (uint32_t)__cvta_generic_to_shared(p);
}
#define CP16(dst_u32, gptr) \
    asm volatile("cp.async.ca.shared.global [%0], [%1], 16;" :: "r"(dst_u32), "l"(gptr))
#define CP_COMMIT() asm volatile("cp.async.commit_group;")
#define CP_WAIT0()  asm volatile("cp.async.wait_group 0;")
#define CP_WAIT1()  asm volatile("cp.async.wait_group 1;")
#define LDMX4(r, addr) \
    asm volatile("ldmatrix.sync.aligned.m8n8.x4.shared.b16 {%0,%1,%2,%3}, [%4];" \
        : "=r"((r)[0]), "=r"((r)[1]), "=r"((r)[2]), "=r"((r)[3]) : "r"(addr))
#define MMA16816(d, a, b) \
    asm volatile("mma.sync.aligned.m16n8k16.row.col.f32.bf16.bf16.f32 " \
        "{%0,%1,%2,%3},{%4,%5,%6,%7},{%8,%9},{%0,%1,%2,%3};\n" \
        : "+f"((d)[0]), "+f"((d)[1]), "+f"((d)[2]), "+f"((d)[3]) \
        : "r"((a)[0]), "r"((a)[1]), "r"((a)[2]), "r"((a)[3]), "r"((b)[0]), "r"((b)[1]))
#define MMA16816H(d, a, b) \
    asm volatile("mma.sync.aligned.m16n8k16.row.col.f32.f16.f16.f32 " \
        "{%0,%1,%2,%3},{%4,%5,%6,%7},{%8,%9},{%0,%1,%2,%3};\n" \
        : "+f"((d)[0]), "+f"((d)[1]), "+f"((d)[2]), "+f"((d)[3]) \
        : "r"((a)[0]), "r"((a)[1]), "r"((a)[2]), "r"((a)[3]), "r"((b)[0]), "r"((b)[1]))

// split pair (a=elem0, b=elem1) into packed bf16x2 hi and lo residual
__device__ __forceinline__ void split2(float a, float b, uint32_t& hi, uint32_t& lo) {
    __nv_bfloat16 ha = __float2bfloat16(a), hb = __float2bfloat16(b);
    __nv_bfloat16 la = __float2bfloat16(a - __bfloat162float(ha));
    __nv_bfloat16 lb = __float2bfloat16(b - __bfloat162float(hb));
    hi = ((uint32_t)__bfloat16_as_ushort(hb) << 16) | (uint32_t)__bfloat16_as_ushort(ha);
    lo = ((uint32_t)__bfloat16_as_ushort(lb) << 16) | (uint32_t)__bfloat16_as_ushort(la);
}

__device__ __forceinline__ uint32_t packh2(float a, float b) {
    __half2 h = __floats2half2_rn(a, b);
    return *reinterpret_cast<uint32_t*>(&h);
}

// ================= prep_x: x -> hi/lo bf16 split ==============
__global__ __launch_bounds__(256) void prep_x_kernel(const float* __restrict__ x) {
    int i = blockIdx.x * 256 + threadIdx.x;     // over float4s (2M floats)
    float4 v = ((const float4*)x)[i];
    uint32_t h0, l0, h1, l1;
    split2(v.x, v.y, h0, l0);
    split2(v.z, v.w, h1, l1);
    uint32_t* hp = (uint32_t*)(g_Ahi + 4*(size_t)i);
    uint32_t* lp = (uint32_t*)(g_Alo + 4*(size_t)i);
    hp[0] = h0; hp[1] = h1;
    lp[0] = l0; lp[1] = l1;
}

// ================= prep_w: W^T hi/lo + mask ==========
__global__ __launch_bounds__(256) void prep_w_kernel(
    const float* __restrict__ Wq, const float* __restrict__ Wk,
    const float* __restrict__ Wv, const float* __restrict__ Wo,
    const unsigned char* __restrict__ raw)
{
    __shared__ float t[32][33];
    __shared__ int mode;
    const int bx = blockIdx.x;
    const int tid = threadIdx.x;

    if (bx < 1024) {
        // ---- W -> W^T hi/lo (32x32 tile transpose) ----
        const int z = bx >> 8;
        const int bxx = bx & 15, byy = (bx >> 4) & 15;
        const float* W = (z == 0) ? Wq : (z == 1) ? Wk : (z == 2) ? Wv : Wo;
        __nv_bfloat16* Th = g_WThi[z];
        __nv_bfloat16* Tl = g_WTlo[z];
        int tx = tid & 31, ty = tid >> 5;       // 32 x 8
        int n0 = bxx * 32, k0 = byy * 32;
        #pragma unroll
        for (int j = 0; j < 4; j++)
            t[ty + 8*j][tx] = W[(size_t)(k0 + ty + 8*j) * HID + n0 + tx];
        __syncthreads();
        #pragma unroll
        for (int j = 0; j < 4; j++) {
            float v = t[tx][ty + 8*j];
            __nv_bfloat16 h = __float2bfloat16(v);
            __nv_bfloat16 l = __float2bfloat16(v - __bfloat162float(h));
            size_t o = (size_t)(n0 + ty + 8*j) * HID + k0 + tx;
            Th[o] = h;
            Tl[o] = l;
        }
    } else {
        // ---- mask normalization (dtype-agnostic) ----
        if (tid == 0) {
            const unsigned int* w = (const unsigned int*)raw;
            int cf = 0, byteish = 0;
            for (int i = 0; i < 128; i++) {
                unsigned int v = w[i];
                if (v == 0x3F800000u) cf++;
                bool b01 = true;
                #pragma unroll
                for (int bb = 0; bb < 4; bb++) {
                    unsigned int by = (v >> (8*bb)) & 0xFFu;
                    if (by > 1u) b01 = false;
                }
                if (b01 && v > 1u) byteish++;
            }
            mode = (cf > 64) ? 0 : ((byteish > 0) ? 2 : 1);  // 0=f32, 1=i32, 2=u8
        }
        __syncthreads();
        int md = mode;
        for (int i = tid; i < NB*SEQ; i += 256) {
            float m;
            if (md == 0)      m = (((const float*)raw)[i] != 0.0f) ? 1.0f : 0.0f;
            else if (md == 1) m = (((const int*)raw)[i]   != 0)    ? 1.0f : 0.0f;
            else              m = (raw[i]                 != 0)    ? 1.0f : 0.0f;
            g_maskf[i] = m;
        }
    }
}

// ================= bf16x3 tensor-core GEMM core (verified R4) =============
#define GBK 32
#define LDT 40
#define BUF_ELEMS (128 * LDT)
#define AH_OFS 0
#define ALO_OFS (2 * BUF_ELEMS)
#define BH_OFS  (4 * BUF_ELEMS)
#define BLO_OFS (6 * BUF_ELEMS)
#define GEMM_SMEM_BYTES (8 * BUF_ELEMS * 2)

__device__ __forceinline__ void bf16x3_gemm(
    const __nv_bfloat16* __restrict__ Ahi, const __nv_bfloat16* __restrict__ Alo,
    const __nv_bfloat16* __restrict__ Bhi, const __nv_bfloat16* __restrict__ Blo,
    int m0, int n0, __nv_bfloat16* sm, float acc[4][4][4])
{
    const int tid = threadIdx.x;
    const int lane = tid & 31, wid = tid >> 5;
    const int wm = wid >> 2, wn = wid & 3;
    const uint32_t smb = sm_u32(sm);

    #pragma unroll
    for (int mi = 0; mi < 4; mi++)
        #pragma unroll
        for (int ni = 0; ni < 4; ni++)
            #pragma unroll
            for (int r = 0; r < 4; r++) acc[mi][ni][r] = 0.0f;

    const int c0 = tid, c1 = tid + 256;
    const int r0 = c0 >> 2, s0 = c0 & 3;
    const int r1 = c1 >> 2, s1 = c1 & 3;

    auto load_chunk = [&](int kc, int buf) {
        const int k0 = kc * GBK;
        const uint32_t so0 = (uint32_t)(buf * BUF_ELEMS + r0 * LDT + s0 * 8) * 2;
        const uint32_t so1 = (uint32_t)(buf * BUF_ELEMS + r1 * LDT + s1 * 8) * 2;
        const size_t ga0 = (size_t)(m0 + r0) * HID + k0 + s0 * 8;
        const size_t ga1 = (size_t)(m0 + r1) * HID + k0 + s1 * 8;
        const size_t gb0 = (size_t)(n0 + r0) * HID + k0 + s0 * 8;
        const size_t gb1 = (size_t)(n0 + r1) * HID + k0 + s1 * 8;
        CP16(smb + AH_OFS*2  + so0, Ahi + ga0);
        CP16(smb + AH_OFS*2  + so1, Ahi + ga1);
        CP16(smb + ALO_OFS*2 + so0, Alo + ga0);
        CP16(smb + ALO_OFS*2 + so1, Alo + ga1);
        CP16(smb + BH_OFS*2  + so0, Bhi + gb0);
        CP16(smb + BH_OFS*2  + so1, Bhi + gb1);
        CP16(smb + BLO_OFS*2 + so0, Blo + gb0);
        CP16(smb + BLO_OFS*2 + so1, Blo + gb1);
    };

    const int arow = wm * 64 + (lane & 15);
    const int acolb = (lane >> 4) << 3;
    const int brow = wn * 32 + (lane & 7) + ((lane & 16) >> 1);
    const int bcolb = lane & 8;

    load_chunk(0, 0);
    CP_COMMIT();

    for (int kc = 0; kc < HID / GBK; kc++) {
        CP_WAIT0();
        __syncthreads();
        if (kc + 1 < HID / GBK) {
            load_chunk(kc + 1, (kc + 1) & 1);
            CP_COMMIT();
        }
        const int buf = kc & 1;
        #pragma unroll
        for (int ks = 0; ks < 2; ks++) {
            uint32_t ah[4][4], al[4][4], bh[2][4], bl[2][4];
            const int acol = ks * 16 + acolb;
            const int bcol = ks * 16 + bcolb;
            #pragma unroll
            for (int mi = 0; mi < 4; mi++) {
                uint32_t off = (uint32_t)(buf * BUF_ELEMS + (arow + mi*16) * LDT + acol) * 2;
                LDMX4(ah[mi], smb + AH_OFS*2 + off);
                LDMX4(al[mi], smb + ALO_OFS*2 + off);
            }
            #pragma unroll
            for (int p = 0; p < 2; p++) {
                uint32_t off = (uint32_t)(buf * BUF_ELEMS + (brow + p*16) * LDT + bcol) * 2;
                LDMX4(bh[p], smb + BH_OFS*2 + off);
                LDMX4(bl[p], smb + BLO_OFS*2 + off);
            }
            #pragma unroll
            for (int mi = 0; mi < 4; mi++)
                #pragma unroll
                for (int ni = 0; ni < 4; ni++) {
                    uint32_t* bhf = &bh[ni >> 1][(ni & 1) * 2];
                    uint32_t* blf = &bl[ni >> 1][(ni & 1) * 2];
                    MMA16816(acc[mi][ni], ah[mi], bhf);
                    MMA16816(acc[mi][ni], ah[mi], blf);
                    MMA16816(acc[mi][ni], al[mi], bhf);
                }
        }
        __syncthreads();
    }
}

// ============ 3-stage pipelined variant (for the 1-wave out-proj) ==========
#define AH3_OFS 0
#define ALO3_OFS (3 * BUF_ELEMS)
#define BH3_OFS  (6 * BUF_ELEMS)
#define BLO3_OFS (9 * BUF_ELEMS)
#define GEMM3_SMEM_BYTES (12 * BUF_ELEMS * 2)   // 122880

__device__ __forceinline__ void bf16x3_gemm3(
    const __nv_bfloat16* __restrict__ Ahi, const __nv_bfloat16* __restrict__ Alo,
    const __nv_bfloat16* __restrict__ Bhi, const __nv_bfloat16* __restrict__ Blo,
    int m0, int n0, __nv_bfloat16* sm, float acc[4][4][4])
{
    const int tid = threadIdx.x;
    const int lane = tid & 31, wid = tid >> 5;
    const int wm = wid >> 2, wn = wid & 3;
    const uint32_t smb = sm_u32(sm);

    #pragma unroll
    for (int mi = 0; mi < 4; mi++)
        #pragma unroll
        for (int ni = 0; ni < 4; ni++)
            #pragma unroll
            for (int r = 0; r < 4; r++) acc[mi][ni][r] = 0.0f;

    const int c0 = tid, c1 = tid + 256;
    const int r0 = c0 >> 2, s0 = c0 & 3;
    const int r1 = c1 >> 2, s1 = c1 & 3;

    auto load_chunk = [&](int kc, int buf) {
        const int k0 = kc * GBK;
        const uint32_t so0 = (uint32_t)(buf * BUF_ELEMS + r0 * LDT + s0 * 8) * 2;
        const uint32_t so1 = (uint32_t)(buf * BUF_ELEMS + r1 * LDT + s1 * 8) * 2;
        const size_t ga0 = (size_t)(m0 + r0) * HID + k0 + s0 * 8;
        const size_t ga1 = (size_t)(m0 + r1) * HID + k0 + s1 * 8;
        const size_t gb0 = (size_t)(n0 + r0) * HID + k0 + s0 * 8;
        const size_t gb1 = (size_t)(n0 + r1) * HID + k0 + s1 * 8;
        CP16(smb + AH3_OFS*2  + so0, Ahi + ga0);
        CP16(smb + AH3_OFS*2  + so1, Ahi + ga1);
        CP16(smb + ALO3_OFS*2 + so0, Alo + ga0);
        CP16(smb + ALO3_OFS*2 + so1, Alo + ga1);
        CP16(smb + BH3_OFS*2  + so0, Bhi + gb0);
        CP16(smb + BH3_OFS*2  + so1, Bhi + gb1);
        CP16(smb + BLO3_OFS*2 + so0, Blo + gb0);
        CP16(smb + BLO3_OFS*2 + so1, Blo + gb1);
    };

    const int arow = wm * 64 + (lane & 15);
    const int acolb = (lane >> 4) << 3;
    const int brow = wn * 32 + (lane & 7) + ((lane & 16) >> 1);
    const int bcolb = lane & 8;

    load_chunk(0, 0);
    CP_COMMIT();
    load_chunk(1, 1);
    CP_COMMIT();

    for (int kc = 0; kc < HID / GBK; kc++) {
        CP_WAIT1();                 // stage kc landed; kc+1 may still fly
        __syncthreads();            // also: all warps done reading buf (kc+2)%3
        if (kc + 2 < HID / GBK) {
            load_chunk(kc + 2, (kc + 2) % 3);
            CP_COMMIT();
        }
        const int buf = kc % 3;
        #pragma unroll
        for (int ks = 0; ks < 2; ks++) {
            uint32_t ah[4][4], al[4][4], bh[2][4], bl[2][4];
            const int acol = ks * 16 + acolb;
            const int bcol = ks * 16 + bcolb;
            #pragma unroll
            for (int mi = 0; mi < 4; mi++) {
                uint32_t off = (uint32_t)(buf * BUF_ELEMS + (arow + mi*16) * LDT + acol) * 2;
                LDMX4(ah[mi], smb + AH3_OFS*2 + off);
                LDMX4(al[mi], smb + ALO3_OFS*2 + off);
            }
            #pragma unroll
            for (int p = 0; p < 2; p++) {
                uint32_t off = (uint32_t)(buf * BUF_ELEMS + (brow + p*16) * LDT + bcol) * 2;
                LDMX4(bh[p], smb + BH3_OFS*2 + off);
                LDMX4(bl[p], smb + BLO3_OFS*2 + off);
            }
            #pragma unroll
            for (int mi = 0; mi < 4; mi++)
                #pragma unroll
                for (int ni = 0; ni < 4; ni++) {
                    uint32_t* bhf = &bh[ni >> 1][(ni & 1) * 2];
                    uint32_t* blf = &bl[ni >> 1][(ni & 1) * 2];
                    MMA16816(acc[mi][ni], ah[mi], bhf);
                    MMA16816(acc[mi][ni], ah[mi], blf);
                    MMA16816(acc[mi][ni], al[mi], bhf);
                }
        }
    }
}

// ---------------- qkv block body (one 128x128 tile of one of Q/K/V) --------
__device__ __forceinline__ void qkv_block(
    int qkv_id, __nv_bfloat16* sm,
    const float* __restrict__ bq, const float* __restrict__ bk,
    const float* __restrict__ bv)
{
    const int z = qkv_id >> 7;            // 0..2
    const int rem = qkv_id & 127;
    const int m0 = (rem >> 2) * 128;      // 32 m-tiles
    const int n0 = (rem & 3) * 128;       // 4 n-tiles
    const float* bias = (z == 0) ? bq : (z == 1) ? bk : bv;

    float acc[4][4][4];
    bf16x3_gemm(g_Ahi, g_Alo, g_WThi[z], g_WTlo[z], m0, n0, sm, acc);

    const int lane = threadIdx.x & 31, wid = threadIdx.x >> 5;
    const int wm = wid >> 2, wn = wid & 3;
    const int g = lane >> 2, tg = lane & 3;
    const float scale = (z == 0) ? 0.125f : 1.0f;

    __half* OUTF = (z == 0) ? g_Qf : g_Kf;

    #pragma unroll
    for (int mi = 0; mi < 4; mi++) {
        #pragma unroll
        for (int ni = 0; ni < 4; ni++) {
            int c = n0 + wn * 32 + ni * 8 + tg * 2;
            int hh = c >> 6, d = c & 63;
            float b0 = bias[c], b1 = bias[c + 1];
            #pragma unroll
            for (int half = 0; half < 2; half++) {
                int m = m0 + wm * 64 + mi * 16 + g + half * 8;
                int bb = m >> 9, n = m & 511;
                int bh = bb * NH + hh;
                float v0 = (acc[mi][ni][half*2 + 0] + b0) * scale;
                float v1 = (acc[mi][ni][half*2 + 1] + b1) * scale;
                if (z < 2) {
                    size_t a = ((size_t)bh * SEQ + n) * HD + d;
                    *(__half2*)&OUTF[a] = __floats2half2_rn(v0, v1);
                } else {
                    // V stored transposed: [b,h,d,n]
                    size_t a0 = ((size_t)bh * HD + d) * SEQ + n;
                    g_VTf[a0]       = __float2half(v0);
                    g_VTf[a0 + SEQ] = __float2half(v1);
                }
            }
        }
    }
}

// -------- dist block: smem-staged coalesced version --------
__device__ __forceinline__ void dist_block(
    int dist_id, char* smraw,
    const float* __restrict__ D, const float* __restrict__ Wd,
    const float* __restrict__ bd)
{
    float* w     = (float*)smraw;
    float* bsm   = (float*)(smraw + 2048);
    float* rows  = (float*)(smraw + 2080);
    __half* outsm = (__half*)(smraw + 71712);
    const uint32_t rows_b = sm_u32(smraw + 2080);
    const int tid = threadIdx.x;

    // stage 256 rows x 256B into smem, fully coalesced 16B chunks
    const float* src = D + (size_t)dist_id * 256 * 64;
    #pragma unroll
    for (int j = 0; j < 16; j++) {
        int c = j * 256 + tid;
        int r = c >> 4, o = c & 15;
        CP16(rows_b + (uint32_t)(r * 272 + o * 16), src + (size_t)c * 4);
    }
    CP_COMMIT();

    w[tid]       = Wd[tid];
    w[tid + 256] = Wd[tid + 256];
    if (tid < 8) bsm[tid] = bd[tid];

    CP_WAIT0();
    __syncthreads();

    // thread-per-row compute from smem (68-float stride: LDS.128 conflict-free)
    const float* rp = rows + tid * 68;
    float acc[8] = {0, 0, 0, 0, 0, 0, 0, 0};
    #pragma unroll
    for (int t = 0; t < 16; t++) {
        float4 v = *(const float4*)(rp + t * 4);
        float vv[4] = {v.x, v.y, v.z, v.w};
        #pragma unroll
        for (int e = 0; e < 4; e++) {
            int d = t * 4 + e;
            #pragma unroll
            for (int h = 0; h < 8; h++)
                acc[h] = fmaf(vv[e], w[d * 8 + h], acc[h]);
        }
    }

    // indices: 256 rows of this block share (b, q); k = k0 + tid
    int b  = dist_id >> 10;
    int rem = (dist_id * 256) & 262143;
    int q  = rem >> 9;
    int k0 = rem & 511;
    // fold key-side mask into bias (-30000 saturates softmax to 0)
    float madd = (g_maskf[b * SEQ + k0 + tid] > 0.5f) ? 0.0f : -30000.0f;
    #pragma unroll
    for (int h = 0; h < 8; h++)
        outsm[h * 256 + tid] = __float2half(acc[h] + bsm[h] + madd);
    __syncthreads();

    // coalesced global write: warp h writes its plane's 512B
    int h = tid >> 5, c = tid & 31;
    uint4 vout = *(const uint4*)&outsm[h * 256 + c * 8];
    *(uint4*)&g_biasf[(((size_t)(b * NH + h)) * SEQ + q) * SEQ + k0 + c * 8] = vout;
}

// ============== fused kernel: qkv GEMM (tensor) ∥ dist_bias (HBM) ==========
// qkv packed into the first 2688 indices (every 7th): the last qkv CTA
// starts at ~90us of the ~146us dist stream and finishes with it (no tail).
__global__ __launch_bounds__(256, 2) void fused_qkv_dist_kernel(
    const float* __restrict__ bq, const float* __restrict__ bk,
    const float* __restrict__ bv,
    const float* __restrict__ D, const float* __restrict__ Wd,
    const float* __restrict__ bd)
{
    extern __shared__ __nv_bfloat16 sm[];
    const int idx = blockIdx.x;
    const bool is_qkv = ((idx % 7) == 0) && (idx < 2688);
    if (is_qkv) {
        qkv_block(idx / 7, sm, bq, bk, bv);
    } else {
        const int nq_before = (idx < 2688) ? (idx / 7 + 1) : 384;
        dist_block(idx - nq_before, (char*)sm, D, Wd, bd);
    }
}

// ---------------- output projection (3-stage pipeline; 1-wave grid) --------
__global__ __launch_bounds__(256) void gemm_out_kernel(
    const float* __restrict__ bo, float* __restrict__ OUT)
{
    extern __shared__ __nv_bfloat16 sm[];
    const int m0 = blockIdx.y * 128, n0 = blockIdx.x * 128;

    float acc[4][4][4];
    bf16x3_gemm3(g_Ahi, g_Alo, g_WThi[3], g_WTlo[3], m0, n0, sm, acc);

    const int lane = threadIdx.x & 31, wid = threadIdx.x >> 5;
    const int wm = wid >> 2, wn = wid & 3;
    const int g = lane >> 2, tg = lane & 3;

    #pragma unroll
    for (int mi = 0; mi < 4; mi++) {
        #pragma unroll
        for (int ni = 0; ni < 4; ni++) {
            int c = n0 + wn * 32 + ni * 8 + tg * 2;
            float b0 = bo[c], b1 = bo[c + 1];
            #pragma unroll
            for (int half = 0; half < 2; half++) {
                int m = m0 + wm * 64 + mi * 16 + g + half * 8;
                float mf = g_maskf[m];
                float2 v;
                v.x = (mf > 0.5f) ? acc[mi][ni][half*2 + 0] + b0 : 0.0f;
                v.y = (mf > 0.5f) ? acc[mi][ni][half*2 + 1] + b1 : 0.0f;
                *(float2*)&OUT[(size_t)m * HID + c] = v;
            }
        }
    }
}

// ======= fp16 tensor-core flash attention, exact softmax w/o running max ===
#define AT_LD 72                      // fp16 row stride (144B, ldmatrix-safe)
#define BT_LD 72
#define OQ 0                          // Q: 128 x AT_LD = 9216 halves
#define OK 9216                       // K: [2 buf][4608]
#define OV 18432                      // V^T: [2 buf][4608]
#define OB 27648                      // bias: [2 buf][9216]
#define ATTN_SMEM_BYTES 92160

__device__ __forceinline__ void attn_load_kv(
    uint32_t smb, int buf, int kb, int tid,
    const __half* Kf, const __half* Vf, const __half* Bb)
{
    const uint32_t bo = (uint32_t)(buf * 4608 * 2);
    #pragma unroll
    for (int j = 0; j < 2; j++) {
        int ch = j * 256 + tid;
        int r = ch >> 3, cc = ch & 7;
        uint32_t so = (uint32_t)((r * AT_LD + cc * 8) * 2);
        CP16(smb + OK*2 + bo + so, Kf + (size_t)(kb * 64 + r) * HD + cc * 8);
        CP16(smb + OV*2 + bo + so, Vf + (size_t)r * SEQ + kb * 64 + cc * 8);
    }
    const uint32_t bob = (uint32_t)(buf * 9216 * 2);
    #pragma unroll
    for (int j = 0; j < 4; j++) {
        int ch = j * 256 + tid;
        int r = ch >> 3, cc = ch & 7;
        uint32_t so = (uint32_t)((r * BT_LD + cc * 8) * 2);
        CP16(smb + OB*2 + bob + so, Bb + (size_t)r * SEQ + kb * 64 + cc * 8);
    }
}

__global__ __launch_bounds__(256, 2) void attn_mma_kernel() {
    extern __shared__ __half smH[];
    const uint32_t smb = sm_u32(smH);
    const int tid = threadIdx.x, lane = tid & 31, w = tid >> 5;   // 8 warps
    const int qb = blockIdx.x, h = blockIdx.y, b = blockIdx.z;
    const int bh = b * NH + h;
    const int g = lane >> 2, t4 = lane & 3;

    const __half* Qf = g_Qf + ((size_t)bh * SEQ + qb * 128) * HD;
    const __half* Kf = g_Kf + (size_t)bh * SEQ * HD;
    const __half* Vf = g_VTf + (size_t)bh * HD * SEQ;
    const __half* Bb = g_biasf + ((size_t)bh * SEQ + qb * 128) * SEQ;

    // Q tile (128 x 64) + first KV+bias tiles
    #pragma unroll
    for (int j = 0; j < 4; j++) {
        int ch = j * 256 + tid;
        int r = ch >> 3, cc = ch & 7;
        uint32_t so = (uint32_t)((r * AT_LD + cc * 8) * 2);
        CP16(smb + OQ*2 + so, Qf + (size_t)r * HD + cc * 8);
    }
    attn_load_kv(smb, 0, 0, tid, Kf, Vf, Bb);
    CP_COMMIT();
    CP_WAIT0();
    __syncthreads();

    // Q fragments; warp w owns rows [w*16, w*16+16)
    uint32_t qf[4][4];
    {
        int arow = w * 16 + (lane & 15);
        int acolb = (lane >> 4) << 3;
        #pragma unroll
        for (int ks = 0; ks < 4; ks++) {
            uint32_t off = (uint32_t)((arow * AT_LD + ks * 16 + acolb) * 2);
            LDMX4(qf[ks], smb + OQ*2 + off);
        }
    }

    float o[4][2][4];
    #pragma unroll
    for (int i = 0; i < 4; i++)
        #pragma unroll
        for (int j = 0; j < 2; j++)
            #pragma unroll
            for (int r = 0; r < 4; r++) o[i][j][r] = 0.0f;
    float lsum[2] = {0.0f, 0.0f};          // per-thread partial row sums

    const int browc = (lane & 7) + ((lane & 16) >> 1);
    const int bcolc = lane & 8;

    for (int kb = 0; kb < 8; kb++) {
        if (kb > 0) { CP_WAIT0(); __syncthreads(); }
        if (kb + 1 < 8) {
            attn_load_kv(smb, (kb + 1) & 1, kb + 1, tid, Kf, Vf, Bb);
            CP_COMMIT();
        }
        const uint32_t bufo  = (uint32_t)((kb & 1) * 4608 * 2);
        const int      bbase = OB + (kb & 1) * 9216;

        // ---- P = exp(Q K^T + bias+mask) directly; no max, no correction ----
        float sv[2][16];
        #pragma unroll
        for (int ni2 = 0; ni2 < 4; ni2++) {
            float s0[4] = {0, 0, 0, 0}, s1[4] = {0, 0, 0, 0};
            #pragma unroll
            for (int ks = 0; ks < 4; ks++) {
                uint32_t off = (uint32_t)(((ni2 * 16 + browc) * AT_LD + ks * 16 + bcolc) * 2);
                uint32_t kf4[4];
                LDMX4(kf4, smb + OK*2 + bufo + off);
                MMA16816H(s0, qf[ks], &kf4[0]);
                MMA16816H(s1, qf[ks], &kf4[2]);
            }
            #pragma unroll
            for (int n8p = 0; n8p < 2; n8p++) {
                const float* sp = n8p ? s1 : s0;
                int lcol = ni2 * 16 + n8p * 8 + t4 * 2;
                #pragma unroll
                for (int rh = 0; rh < 2; rh++) {
                    __half2 bb = *(const __half2*)
                        &smH[bbase + (w * 16 + g + rh * 8) * BT_LD + lcol];
                    float2 bf = __half22float2(bb);
                    float p0 = __expf(sp[rh*2 + 0] + bf.x);
                    float p1 = __expf(sp[rh*2 + 1] + bf.y);
                    sv[rh][ni2*4 + n8p*2 + 0] = p0;
                    sv[rh][ni2*4 + n8p*2 + 1] = p1;
                    lsum[rh] += p0 + p1;
                }
            }
        }

        // ---- O += P V (fp16 single pass) ----
        #pragma unroll
        for (int ks = 0; ks < 4; ks++) {
            uint32_t pf[4];
            pf[0] = packh2(sv[0][ks*4 + 0], sv[0][ks*4 + 1]);
            pf[1] = packh2(sv[1][ks*4 + 0], sv[1][ks*4 + 1]);
            pf[2] = packh2(sv[0][ks*4 + 2], sv[0][ks*4 + 3]);
            pf[3] = packh2(sv[1][ks*4 + 2], sv[1][ks*4 + 3]);
            #pragma unroll
            for (int ni2 = 0; ni2 < 4; ni2++) {
                uint32_t off = (uint32_t)(((ni2 * 16 + browc) * AT_LD + ks * 16 + bcolc) * 2);
                uint32_t vf4[4];
                LDMX4(vf4, smb + OV*2 + bufo + off);
                MMA16816H(o[ni2][0], pf, &vf4[0]);
                MMA16816H(o[ni2][1], pf, &vf4[2]);
            }
        }
    }

    // ---- final row-sum reduction (once) + epilogue ----
    #pragma unroll
    for (int rh = 0; rh < 2; rh++) {
        lsum[rh] += __shfl_xor_sync(0xffffffffu, lsum[rh], 1);
        lsum[rh] += __shfl_xor_sync(0xffffffffu, lsum[rh], 2);
    }
    float inv[2] = {1.0f / lsum[0], 1.0f / lsum[1]};
    #pragma unroll
    for (int ni2 = 0; ni2 < 4; ni2++) {
        #pragma unroll
        for (int n8p = 0; n8p < 2; n8p++) {
            int col = h * 64 + ni2 * 16 + n8p * 8 + t4 * 2;
            #pragma unroll
            for (int rh = 0; rh < 2; rh++) {
                size_t m = (size_t)b * SEQ + qb * 128 + w * 16 + g + rh * 8;
                float v0 = o[ni2][n8p][rh*2 + 0] * inv[rh];
                float v1 = o[ni2][n8p][rh*2 + 1] * inv[rh];
                uint32_t hiw, low;
                split2(v0, v1, hiw, low);
                *(uint32_t*)&g_Ahi[m * HID + col] = hiw;
                *(uint32_t*)&g_Alo[m * HID + col] = low;
            }
        }
    }
}

// ---------------- launch ----------------
extern "C" void kernel_launch(void* const* d_in, const int* in_sizes, int n_in,
                              void* d_out, int out_size)
{
    const float* x    = (const float*)d_in[0];
    const float* dist = (const float*)d_in[1];
    const unsigned char* mask = (const unsigned char*)d_in[2];
    const float* Wq = (const float*)d_in[3];
    const float* bq = (const float*)d_in[4];
    const float* Wk = (const float*)d_in[5];
    const float* bk = (const float*)d_in[6];
    const float* Wv = (const float*)d_in[7];
    const float* bv = (const float*)d_in[8];
    const float* Wo = (const float*)d_in[9];
    const float* bo = (const float*)d_in[10];
    const float* Wd = (const float*)d_in[11];
    const float* bd = (const float*)d_in[12];
    float* out = (float*)d_out;

    cudaFuncSetAttribute(fused_qkv_dist_kernel, cudaFuncAttributeMaxDynamicSharedMemorySize,
                         GEMM_SMEM_BYTES);
    cudaFuncSetAttribute(gemm_out_kernel, cudaFuncAttributeMaxDynamicSharedMemorySize,
                         GEMM3_SMEM_BYTES);
    cudaFuncSetAttribute(attn_mma_kernel, cudaFuncAttributeMaxDynamicSharedMemorySize,
                         ATTN_SMEM_BYTES);

    prep_x_kernel<<<2048, 256>>>(x);
    prep_w_kernel<<<1025, 256>>>(Wq, Wk, Wv, Wo, mask);
    fused_qkv_dist_kernel<<<8576, 256, GEMM_SMEM_BYTES>>>(bq, bk, bv, dist, Wd, bd);
    attn_mma_kernel<<<dim3(4, NH, NB), 256, ATTN_SMEM_BYTES>>>();
    gemm_out_kernel<<<dim3(4, 32), 256, GEMM3_SMEM_BYTES>>>(bo, out);
}

// round 15
// speedup vs baseline: 1.3352x; 1.1123x over previous
#include <cuda_runtime.h>
#include <cuda_bf16.h>
#include <cuda_fp16.h>
#include <stdint.h>
#include <math.h>

#define NB 8
#define NH 8
#define SEQ 512
#define HID 512
#define HD 64

// ---------------- scratch (device globals; no allocations) ----------------
__device__ float g_maskf[NB*SEQ];                        // 0/1 floats
__device__ __half g_biasf[(size_t)NB*NH*SEQ*SEQ];        // 32 MB fp16 bias (+key mask)
__device__ __half g_Xf[NB*SEQ*HID];                      // x in fp16 (qkv A operand)
__device__ __half g_WTf[3][HID*HID];                     // W^T fp16 for q,k,v
__device__ __half g_Qf[NB*NH*SEQ*HD];                    // [b,h,n,d] (pre-scaled)
__device__ __half g_Kf[NB*NH*SEQ*HD];                    // [b,h,n,d]
__device__ __half g_VTf[NB*NH*SEQ*HD];                   // [b,h,d,n]
__device__ __nv_bfloat16 g_Ahi[NB*SEQ*HID], g_Alo[NB*SEQ*HID];   // ctx hi/lo
__device__ __nv_bfloat16 g_WThi[1][HID*HID], g_WTlo[1][HID*HID]; // Wo^T hi/lo

// ---------------- PTX helpers ----------------
__device__ __forceinline__ uint32_t sm_u32(const void* p) {
    return (uint32_t)__cvta_generic_to_shared(p);
}
#define CP16(dst_u32, gptr) \
    asm volatile("cp.async.ca.shared.global [%0], [%1], 16;" :: "r"(dst_u32), "l"(gptr))
#define CP_COMMIT() asm volatile("cp.async.commit_group;")
#define CP_WAIT0()  asm volatile("cp.async.wait_group 0;")
#define CP_WAIT1()  asm volatile("cp.async.wait_group 1;")
#define LDMX4(r, addr) \
    asm volatile("ldmatrix.sync.aligned.m8n8.x4.shared.b16 {%0,%1,%2,%3}, [%4];" \
        : "=r"((r)[0]), "=r"((r)[1]), "=r"((r)[2]), "=r"((r)[3]) : "r"(addr))
#define MMA16816(d, a, b) \
    asm volatile("mma.sync.aligned.m16n8k16.row.col.f32.bf16.bf16.f32 " \
        "{%0,%1,%2,%3},{%4,%5,%6,%7},{%8,%9},{%0,%1,%2,%3};\n" \
        : "+f"((d)[0]), "+f"((d)[1]), "+f"((d)[2]), "+f"((d)[3]) \
        : "r"((a)[0]), "r"((a)[1]), "r"((a)[2]), "r"((a)[3]), "r"((b)[0]), "r"((b)[1]))
#define MMA16816H(d, a, b) \
    asm volatile("mma.sync.aligned.m16n8k16.row.col.f32.f16.f16.f32 " \
        "{%0,%1,%2,%3},{%4,%5,%6,%7},{%8,%9},{%0,%1,%2,%3};\n" \
        : "+f"((d)[0]), "+f"((d)[1]), "+f"((d)[2]), "+f"((d)[3]) \
        : "r"((a)[0]), "r"((a)[1]), "r"((a)[2]), "r"((a)[3]), "r"((b)[0]), "r"((b)[1]))

// split pair (a=elem0, b=elem1) into packed bf16x2 hi and lo residual
__device__ __forceinline__ void split2(float a, float b, uint32_t& hi, uint32_t& lo) {
    __nv_bfloat16 ha = __float2bfloat16(a), hb = __float2bfloat16(b);
    __nv_bfloat16 la = __float2bfloat16(a - __bfloat162float(ha));
    __nv_bfloat16 lb = __float2bfloat16(b - __bfloat162float(hb));
    hi = ((uint32_t)__bfloat16_as_ushort(hb) << 16) | (uint32_t)__bfloat16_as_ushort(ha);
    lo = ((uint32_t)__bfloat16_as_ushort(lb) << 16) | (uint32_t)__bfloat16_as_ushort(la);
}

__device__ __forceinline__ uint32_t packh2(float a, float b) {
    __half2 h = __floats2half2_rn(a, b);
    return *reinterpret_cast<uint32_t*>(&h);
}

// ================= prep_x: x -> fp16 ==============
__global__ __launch_bounds__(256) void prep_x_kernel(const float* __restrict__ x) {
    int i = blockIdx.x * 256 + threadIdx.x;     // over float4s (2M floats)
    float4 v = ((const float4*)x)[i];
    uint32_t* xp = (uint32_t*)(g_Xf + 4*(size_t)i);
    xp[0] = packh2(v.x, v.y);
    xp[1] = packh2(v.z, v.w);
}

// ================= prep_w: Wq/k/v^T fp16, Wo^T bf16 hi/lo, mask ============
__global__ __launch_bounds__(256) void prep_w_kernel(
    const float* __restrict__ Wq, const float* __restrict__ Wk,
    const float* __restrict__ Wv, const float* __restrict__ Wo,
    const unsigned char* __restrict__ raw)
{
    __shared__ float t[32][33];
    __shared__ int mode;
    const int bx = blockIdx.x;
    const int tid = threadIdx.x;

    if (bx < 1024) {
        // ---- W -> W^T (32x32 tile transpose) ----
        const int z = bx >> 8;
        const int bxx = bx & 15, byy = (bx >> 4) & 15;
        const float* W = (z == 0) ? Wq : (z == 1) ? Wk : (z == 2) ? Wv : Wo;
        int tx = tid & 31, ty = tid >> 5;       // 32 x 8
        int n0 = bxx * 32, k0 = byy * 32;
        #pragma unroll
        for (int j = 0; j < 4; j++)
            t[ty + 8*j][tx] = W[(size_t)(k0 + ty + 8*j) * HID + n0 + tx];
        __syncthreads();
        #pragma unroll
        for (int j = 0; j < 4; j++) {
            float v = t[tx][ty + 8*j];
            size_t o = (size_t)(n0 + ty + 8*j) * HID + k0 + tx;
            if (z < 3) {
                g_WTf[z][o] = __float2half(v);
            } else {
                __nv_bfloat16 h = __float2bfloat16(v);
                __nv_bfloat16 l = __float2bfloat16(v - __bfloat162float(h));
                g_WThi[0][o] = h;
                g_WTlo[0][o] = l;
            }
        }
    } else {
        // ---- mask normalization (dtype-agnostic) ----
        if (tid == 0) {
            const unsigned int* w = (const unsigned int*)raw;
            int cf = 0, byteish = 0;
            for (int i = 0; i < 128; i++) {
                unsigned int v = w[i];
                if (v == 0x3F800000u) cf++;
                bool b01 = true;
                #pragma unroll
                for (int bb = 0; bb < 4; bb++) {
                    unsigned int by = (v >> (8*bb)) & 0xFFu;
                    if (by > 1u) b01 = false;
                }
                if (b01 && v > 1u) byteish++;
            }
            mode = (cf > 64) ? 0 : ((byteish > 0) ? 2 : 1);  // 0=f32, 1=i32, 2=u8
        }
        __syncthreads();
        int md = mode;
        for (int i = tid; i < NB*SEQ; i += 256) {
            float m;
            if (md == 0)      m = (((const float*)raw)[i] != 0.0f) ? 1.0f : 0.0f;
            else if (md == 1) m = (((const int*)raw)[i]   != 0)    ? 1.0f : 0.0f;
            else              m = (raw[i]                 != 0)    ? 1.0f : 0.0f;
            g_maskf[i] = m;
        }
    }
}

// ================= shared tile constants =============
#define GBK 32
#define LDT 40
#define BUF_ELEMS (128 * LDT)
#define GEMM_SMEM_BYTES 81920

// ================= fp16 single-pass GEMM (qkv) =================
// A[m][k], B[n][k] fp16; double-buffered; 16 mma per k-chunk.
#define HA_OFS 0
#define HB_OFS (2 * BUF_ELEMS)

__device__ __forceinline__ void fp16_gemm(
    const __half* __restrict__ A, const __half* __restrict__ B,
    int m0, int n0, __half* sm, float acc[4][4][4])
{
    const int tid = threadIdx.x;
    const int lane = tid & 31, wid = tid >> 5;
    const int wm = wid >> 2, wn = wid & 3;
    const uint32_t smb = sm_u32(sm);

    #pragma unroll
    for (int mi = 0; mi < 4; mi++)
        #pragma unroll
        for (int ni = 0; ni < 4; ni++)
            #pragma unroll
            for (int r = 0; r < 4; r++) acc[mi][ni][r] = 0.0f;

    const int c0 = tid, c1 = tid + 256;
    const int r0 = c0 >> 2, s0 = c0 & 3;
    const int r1 = c1 >> 2, s1 = c1 & 3;

    auto load_chunk = [&](int kc, int buf) {
        const int k0 = kc * GBK;
        const uint32_t so0 = (uint32_t)(buf * BUF_ELEMS + r0 * LDT + s0 * 8) * 2;
        const uint32_t so1 = (uint32_t)(buf * BUF_ELEMS + r1 * LDT + s1 * 8) * 2;
        CP16(smb + HA_OFS*2 + so0, A + (size_t)(m0 + r0) * HID + k0 + s0 * 8);
        CP16(smb + HA_OFS*2 + so1, A + (size_t)(m0 + r1) * HID + k0 + s1 * 8);
        CP16(smb + HB_OFS*2 + so0, B + (size_t)(n0 + r0) * HID + k0 + s0 * 8);
        CP16(smb + HB_OFS*2 + so1, B + (size_t)(n0 + r1) * HID + k0 + s1 * 8);
    };

    const int arow = wm * 64 + (lane & 15);
    const int acolb = (lane >> 4) << 3;
    const int brow = wn * 32 + (lane & 7) + ((lane & 16) >> 1);
    const int bcolb = lane & 8;

    load_chunk(0, 0);
    CP_COMMIT();

    for (int kc = 0; kc < HID / GBK; kc++) {
        CP_WAIT0();
        __syncthreads();
        if (kc + 1 < HID / GBK) {
            load_chunk(kc + 1, (kc + 1) & 1);
            CP_COMMIT();
        }
        const int buf = kc & 1;
        #pragma unroll
        for (int ks = 0; ks < 2; ks++) {
            uint32_t ah[4][4], bh[2][4];
            const int acol = ks * 16 + acolb;
            const int bcol = ks * 16 + bcolb;
            #pragma unroll
            for (int mi = 0; mi < 4; mi++) {
                uint32_t off = (uint32_t)(buf * BUF_ELEMS + (arow + mi*16) * LDT + acol) * 2;
                LDMX4(ah[mi], smb + HA_OFS*2 + off);
            }
            #pragma unroll
            for (int p = 0; p < 2; p++) {
                uint32_t off = (uint32_t)(buf * BUF_ELEMS + (brow + p*16) * LDT + bcol) * 2;
                LDMX4(bh[p], smb + HB_OFS*2 + off);
            }
            #pragma unroll
            for (int mi = 0; mi < 4; mi++)
                #pragma unroll
                for (int ni = 0; ni < 4; ni++)
                    MMA16816H(acc[mi][ni], ah[mi], &bh[ni >> 1][(ni & 1) * 2]);
        }
        __syncthreads();
    }
}

// ============ bf16x3 3-stage pipelined GEMM (out-proj only) ==========
#define AH3_OFS 0
#define ALO3_OFS (3 * BUF_ELEMS)
#define BH3_OFS  (6 * BUF_ELEMS)
#define BLO3_OFS (9 * BUF_ELEMS)
#define GEMM3_SMEM_BYTES (12 * BUF_ELEMS * 2)   // 122880

__device__ __forceinline__ void bf16x3_gemm3(
    const __nv_bfloat16* __restrict__ Ahi, const __nv_bfloat16* __restrict__ Alo,
    const __nv_bfloat16* __restrict__ Bhi, const __nv_bfloat16* __restrict__ Blo,
    int m0, int n0, __nv_bfloat16* sm, float acc[4][4][4])
{
    const int tid = threadIdx.x;
    const int lane = tid & 31, wid = tid >> 5;
    const int wm = wid >> 2, wn = wid & 3;
    const uint32_t smb = sm_u32(sm);

    #pragma unroll
    for (int mi = 0; mi < 4; mi++)
        #pragma unroll
        for (int ni = 0; ni < 4; ni++)
            #pragma unroll
            for (int r = 0; r < 4; r++) acc[mi][ni][r] = 0.0f;

    const int c0 = tid, c1 = tid + 256;
    const int r0 = c0 >> 2, s0 = c0 & 3;
    const int r1 = c1 >> 2, s1 = c1 & 3;

    auto load_chunk = [&](int kc, int buf) {
        const int k0 = kc * GBK;
        const uint32_t so0 = (uint32_t)(buf * BUF_ELEMS + r0 * LDT + s0 * 8) * 2;
        const uint32_t so1 = (uint32_t)(buf * BUF_ELEMS + r1 * LDT + s1 * 8) * 2;
        const size_t ga0 = (size_t)(m0 + r0) * HID + k0 + s0 * 8;
        const size_t ga1 = (size_t)(m0 + r1) * HID + k0 + s1 * 8;
        const size_t gb0 = (size_t)(n0 + r0) * HID + k0 + s0 * 8;
        const size_t gb1 = (size_t)(n0 + r1) * HID + k0 + s1 * 8;
        CP16(smb + AH3_OFS*2  + so0, Ahi + ga0);
        CP16(smb + AH3_OFS*2  + so1, Ahi + ga1);
        CP16(smb + ALO3_OFS*2 + so0, Alo + ga0);
        CP16(smb + ALO3_OFS*2 + so1, Alo + ga1);
        CP16(smb + BH3_OFS*2  + so0, Bhi + gb0);
        CP16(smb + BH3_OFS*2  + so1, Bhi + gb1);
        CP16(smb + BLO3_OFS*2 + so0, Blo + gb0);
        CP16(smb + BLO3_OFS*2 + so1, Blo + gb1);
    };

    const int arow = wm * 64 + (lane & 15);
    const int acolb = (lane >> 4) << 3;
    const int brow = wn * 32 + (lane & 7) + ((lane & 16) >> 1);
    const int bcolb = lane & 8;

    load_chunk(0, 0);
    CP_COMMIT();
    load_chunk(1, 1);
    CP_COMMIT();

    for (int kc = 0; kc < HID / GBK; kc++) {
        CP_WAIT1();
        __syncthreads();
        if (kc + 2 < HID / GBK) {
            load_chunk(kc + 2, (kc + 2) % 3);
            CP_COMMIT();
        }
        const int buf = kc % 3;
        #pragma unroll
        for (int ks = 0; ks < 2; ks++) {
            uint32_t ah[4][4], al[4][4], bh[2][4], bl[2][4];
            const int acol = ks * 16 + acolb;
            const int bcol = ks * 16 + bcolb;
            #pragma unroll
            for (int mi = 0; mi < 4; mi++) {
                uint32_t off = (uint32_t)(buf * BUF_ELEMS + (arow + mi*16) * LDT + acol) * 2;
                LDMX4(ah[mi], smb + AH3_OFS*2 + off);
                LDMX4(al[mi], smb + ALO3_OFS*2 + off);
            }
            #pragma unroll
            for (int p = 0; p < 2; p++) {
                uint32_t off = (uint32_t)(buf * BUF_ELEMS + (brow + p*16) * LDT + bcol) * 2;
                LDMX4(bh[p], smb + BH3_OFS*2 + off);
                LDMX4(bl[p], smb + BLO3_OFS*2 + off);
            }
            #pragma unroll
            for (int mi = 0; mi < 4; mi++)
                #pragma unroll
                for (int ni = 0; ni < 4; ni++) {
                    uint32_t* bhf = &bh[ni >> 1][(ni & 1) * 2];
                    uint32_t* blf = &bl[ni >> 1][(ni & 1) * 2];
                    MMA16816(acc[mi][ni], ah[mi], bhf);
                    MMA16816(acc[mi][ni], ah[mi], blf);
                    MMA16816(acc[mi][ni], al[mi], bhf);
                }
        }
    }
}

// ---------------- qkv block body (fp16 single pass) --------
__device__ __forceinline__ void qkv_block(
    int qkv_id, __half* sm,
    const float* __restrict__ bq, const float* __restrict__ bk,
    const float* __restrict__ bv)
{
    const int z = qkv_id >> 7;            // 0..2
    const int rem = qkv_id & 127;
    const int m0 = (rem >> 2) * 128;      // 32 m-tiles
    const int n0 = (rem & 3) * 128;       // 4 n-tiles
    const float* bias = (z == 0) ? bq : (z == 1) ? bk : bv;

    float acc[4][4][4];
    fp16_gemm(g_Xf, g_WTf[z], m0, n0, sm, acc);

    const int lane = threadIdx.x & 31, wid = threadIdx.x >> 5;
    const int wm = wid >> 2, wn = wid & 3;
    const int g = lane >> 2, tg = lane & 3;
    const float scale = (z == 0) ? 0.125f : 1.0f;

    __half* OUTF = (z == 0) ? g_Qf : g_Kf;

    #pragma unroll
    for (int mi = 0; mi < 4; mi++) {
        #pragma unroll
        for (int ni = 0; ni < 4; ni++) {
            int c = n0 + wn * 32 + ni * 8 + tg * 2;
            int hh = c >> 6, d = c & 63;
            float b0 = bias[c], b1 = bias[c + 1];
            #pragma unroll
            for (int half = 0; half < 2; half++) {
                int m = m0 + wm * 64 + mi * 16 + g + half * 8;
                int bb = m >> 9, n = m & 511;
                int bh = bb * NH + hh;
                float v0 = (acc[mi][ni][half*2 + 0] + b0) * scale;
                float v1 = (acc[mi][ni][half*2 + 1] + b1) * scale;
                if (z < 2) {
                    size_t a = ((size_t)bh * SEQ + n) * HD + d;
                    *(__half2*)&OUTF[a] = __floats2half2_rn(v0, v1);
                } else {
                    // V stored transposed: [b,h,d,n]
                    size_t a0 = ((size_t)bh * HD + d) * SEQ + n;
                    g_VTf[a0]       = __float2half(v0);
                    g_VTf[a0 + SEQ] = __float2half(v1);
                }
            }
        }
    }
}

// -------- dist block: smem-staged coalesced version --------
__device__ __forceinline__ void dist_block(
    int dist_id, char* smraw,
    const float* __restrict__ D, const float* __restrict__ Wd,
    const float* __restrict__ bd)
{
    float* w     = (float*)smraw;
    float* bsm   = (float*)(smraw + 2048);
    float* rows  = (float*)(smraw + 2080);
    __half* outsm = (__half*)(smraw + 71712);
    const uint32_t rows_b = sm_u32(smraw + 2080);
    const int tid = threadIdx.x;

    // stage 256 rows x 256B into smem, fully coalesced 16B chunks
    const float* src = D + (size_t)dist_id * 256 * 64;
    #pragma unroll
    for (int j = 0; j < 16; j++) {
        int c = j * 256 + tid;
        int r = c >> 4, o = c & 15;
        CP16(rows_b + (uint32_t)(r * 272 + o * 16), src + (size_t)c * 4);
    }
    CP_COMMIT();

    w[tid]       = Wd[tid];
    w[tid + 256] = Wd[tid + 256];
    if (tid < 8) bsm[tid] = bd[tid];

    CP_WAIT0();
    __syncthreads();

    // thread-per-row compute from smem (68-float stride: LDS.128 conflict-free)
    const float* rp = rows + tid * 68;
    float acc[8] = {0, 0, 0, 0, 0, 0, 0, 0};
    #pragma unroll
    for (int t = 0; t < 16; t++) {
        float4 v = *(const float4*)(rp + t * 4);
        float vv[4] = {v.x, v.y, v.z, v.w};
        #pragma unroll
        for (int e = 0; e < 4; e++) {
            int d = t * 4 + e;
            #pragma unroll
            for (int h = 0; h < 8; h++)
                acc[h] = fmaf(vv[e], w[d * 8 + h], acc[h]);
        }
    }

    // indices: 256 rows of this block share (b, q); k = k0 + tid
    int b  = dist_id >> 10;
    int rem = (dist_id * 256) & 262143;
    int q  = rem >> 9;
    int k0 = rem & 511;
    // fold key-side mask into bias (-30000 saturates softmax to 0)
    float madd = (g_maskf[b * SEQ + k0 + tid] > 0.5f) ? 0.0f : -30000.0f;
    #pragma unroll
    for (int h = 0; h < 8; h++)
        outsm[h * 256 + tid] = __float2half(acc[h] + bsm[h] + madd);
    __syncthreads();

    // coalesced global write: warp h writes its plane's 512B
    int h = tid >> 5, c = tid & 31;
    uint4 vout = *(const uint4*)&outsm[h * 256 + c * 8];
    *(uint4*)&g_biasf[(((size_t)(b * NH + h)) * SEQ + q) * SEQ + k0 + c * 8] = vout;
}

// ============== fused kernel: qkv GEMM (tensor) ∥ dist_bias (HBM) ==========
__global__ __launch_bounds__(256, 2) void fused_qkv_dist_kernel(
    const float* __restrict__ bq, const float* __restrict__ bk,
    const float* __restrict__ bv,
    const float* __restrict__ D, const float* __restrict__ Wd,
    const float* __restrict__ bd)
{
    extern __shared__ __half smg[];
    const int idx = blockIdx.x;
    const bool is_qkv = ((idx % 7) == 0) && (idx < 2688);
    if (is_qkv) {
        qkv_block(idx / 7, smg, bq, bk, bv);
    } else {
        const int nq_before = (idx < 2688) ? (idx / 7 + 1) : 384;
        dist_block(idx - nq_before, (char*)smg, D, Wd, bd);
    }
}

// ---------------- output projection (3-stage pipeline; 1-wave grid) --------
__global__ __launch_bounds__(256) void gemm_out_kernel(
    const float* __restrict__ bo, float* __restrict__ OUT)
{
    extern __shared__ __nv_bfloat16 smo[];
    const int m0 = blockIdx.y * 128, n0 = blockIdx.x * 128;

    float acc[4][4][4];
    bf16x3_gemm3(g_Ahi, g_Alo, g_WThi[0], g_WTlo[0], m0, n0, smo, acc);

    const int lane = threadIdx.x & 31, wid = threadIdx.x >> 5;
    const int wm = wid >> 2, wn = wid & 3;
    const int g = lane >> 2, tg = lane & 3;

    #pragma unroll
    for (int mi = 0; mi < 4; mi++) {
        #pragma unroll
        for (int ni = 0; ni < 4; ni++) {
            int c = n0 + wn * 32 + ni * 8 + tg * 2;
            float b0 = bo[c], b1 = bo[c + 1];
            #pragma unroll
            for (int half = 0; half < 2; half++) {
                int m = m0 + wm * 64 + mi * 16 + g + half * 8;
                float mf = g_maskf[m];
                float2 v;
                v.x = (mf > 0.5f) ? acc[mi][ni][half*2 + 0] + b0 : 0.0f;
                v.y = (mf > 0.5f) ? acc[mi][ni][half*2 + 1] + b1 : 0.0f;
                *(float2*)&OUT[(size_t)m * HID + c] = v;
            }
        }
    }
}

// ======= fp16 tensor-core flash attention, exact softmax w/o running max ===
#define AT_LD 72                      // fp16 row stride (144B, ldmatrix-safe)
#define BT_LD 72
#define OQ 0                          // Q: 128 x AT_LD = 9216 halves
#define OK 9216                       // K: [2 buf][4608]
#define OV 18432                      // V^T: [2 buf][4608]
#define OB 27648                      // bias: [2 buf][9216]
#define ATTN_SMEM_BYTES 92160

__device__ __forceinline__ void attn_load_kv(
    uint32_t smb, int buf, int kb, int tid,
    const __half* Kf, const __half* Vf, const __half* Bb)
{
    const uint32_t bo = (uint32_t)(buf * 4608 * 2);
    #pragma unroll
    for (int j = 0; j < 2; j++) {
        int ch = j * 256 + tid;
        int r = ch >> 3, cc = ch & 7;
        uint32_t so = (uint32_t)((r * AT_LD + cc * 8) * 2);
        CP16(smb + OK*2 + bo + so, Kf + (size_t)(kb * 64 + r) * HD + cc * 8);
        CP16(smb + OV*2 + bo + so, Vf + (size_t)r * SEQ + kb * 64 + cc * 8);
    }
    const uint32_t bob = (uint32_t)(buf * 9216 * 2);
    #pragma unroll
    for (int j = 0; j < 4; j++) {
        int ch = j * 256 + tid;
        int r = ch >> 3, cc = ch & 7;
        uint32_t so = (uint32_t)((r * BT_LD + cc * 8) * 2);
        CP16(smb + OB*2 + bob + so, Bb + (size_t)r * SEQ + kb * 64 + cc * 8);
    }
}

__global__ __launch_bounds__(256, 2) void attn_mma_kernel() {
    extern __shared__ __half smH[];
    const uint32_t smb = sm_u32(smH);
    const int tid = threadIdx.x, lane = tid & 31, w = tid >> 5;   // 8 warps
    const int qb = blockIdx.x, h = blockIdx.y, b = blockIdx.z;
    const int bh = b * NH + h;
    const int g = lane >> 2, t4 = lane & 3;

    const __half* Qf = g_Qf + ((size_t)bh * SEQ + qb * 128) * HD;
    const __half* Kf = g_Kf + (size_t)bh * SEQ * HD;
    const __half* Vf = g_VTf + (size_t)bh * HD * SEQ;
    const __half* Bb = g_biasf + ((size_t)bh * SEQ + qb * 128) * SEQ;

    // Q tile (128 x 64) + first KV+bias tiles
    #pragma unroll
    for (int j = 0; j < 4; j++) {
        int ch = j * 256 + tid;
        int r = ch >> 3, cc = ch & 7;
        uint32_t so = (uint32_t)((r * AT_LD + cc * 8) * 2);
        CP16(smb + OQ*2 + so, Qf + (size_t)r * HD + cc * 8);
    }
    attn_load_kv(smb, 0, 0, tid, Kf, Vf, Bb);
    CP_COMMIT();
    CP_WAIT0();
    __syncthreads();

    // Q fragments; warp w owns rows [w*16, w*16+16)
    uint32_t qf[4][4];
    {
        int arow = w * 16 + (lane & 15);
        int acolb = (lane >> 4) << 3;
        #pragma unroll
        for (int ks = 0; ks < 4; ks++) {
            uint32_t off = (uint32_t)((arow * AT_LD + ks * 16 + acolb) * 2);
            LDMX4(qf[ks], smb + OQ*2 + off);
        }
    }

    float o[4][2][4];
    #pragma unroll
    for (int i = 0; i < 4; i++)
        #pragma unroll
        for (int j = 0; j < 2; j++)
            #pragma unroll
            for (int r = 0; r < 4; r++) o[i][j][r] = 0.0f;
    float lsum[2] = {0.0f, 0.0f};          // per-thread partial row sums

    const int browc = (lane & 7) + ((lane & 16) >> 1);
    const int bcolc = lane & 8;

    for (int kb = 0; kb < 8; kb++) {
        if (kb > 0) { CP_WAIT0(); __syncthreads(); }
        if (kb + 1 < 8) {
            attn_load_kv(smb, (kb + 1) & 1, kb + 1, tid, Kf, Vf, Bb);
            CP_COMMIT();
        }
        const uint32_t bufo  = (uint32_t)((kb & 1) * 4608 * 2);
        const int      bbase = OB + (kb & 1) * 9216;

        // ---- P = exp(Q K^T + bias+mask) directly; no max, no correction ----
        float sv[2][16];
        #pragma unroll
        for (int ni2 = 0; ni2 < 4; ni2++) {
            float s0[4] = {0, 0, 0, 0}, s1[4] = {0, 0, 0, 0};
            #pragma unroll
            for (int ks = 0; ks < 4; ks++) {
                uint32_t off = (uint32_t)(((ni2 * 16 + browc) * AT_LD + ks * 16 + bcolc) * 2);
                uint32_t kf4[4];
                LDMX4(kf4, smb + OK*2 + bufo + off);
                MMA16816H(s0, qf[ks], &kf4[0]);
                MMA16816H(s1, qf[ks], &kf4[2]);
            }
            #pragma unroll
            for (int n8p = 0; n8p < 2; n8p++) {
                const float* sp = n8p ? s1 : s0;
                int lcol = ni2 * 16 + n8p * 8 + t4 * 2;
                #pragma unroll
                for (int rh = 0; rh < 2; rh++) {
                    __half2 bb = *(const __half2*)
                        &smH[bbase + (w * 16 + g + rh * 8) * BT_LD + lcol];
                    float2 bf = __half22float2(bb);
                    float p0 = __expf(sp[rh*2 + 0] + bf.x);
                    float p1 = __expf(sp[rh*2 + 1] + bf.y);
                    sv[rh][ni2*4 + n8p*2 + 0] = p0;
                    sv[rh][ni2*4 + n8p*2 + 1] = p1;
                    lsum[rh] += p0 + p1;
                }
            }
        }

        // ---- O += P V (fp16 single pass) ----
        #pragma unroll
        for (int ks = 0; ks < 4; ks++) {
            uint32_t pf[4];
            pf[0] = packh2(sv[0][ks*4 + 0], sv[0][ks*4 + 1]);
            pf[1] = packh2(sv[1][ks*4 + 0], sv[1][ks*4 + 1]);
            pf[2] = packh2(sv[0][ks*4 + 2], sv[0][ks*4 + 3]);
            pf[3] = packh2(sv[1][ks*4 + 2], sv[1][ks*4 + 3]);
            #pragma unroll
            for (int ni2 = 0; ni2 < 4; ni2++) {
                uint32_t off = (uint32_t)(((ni2 * 16 + browc) * AT_LD + ks * 16 + bcolc) * 2);
                uint32_t vf4[4];
                LDMX4(vf4, smb + OV*2 + bufo + off);
                MMA16816H(o[ni2][0], pf, &vf4[0]);
                MMA16816H(o[ni2][1], pf, &vf4[2]);
            }
        }
    }

    // ---- final row-sum reduction (once) + epilogue ----
    #pragma unroll
    for (int rh = 0; rh < 2; rh++) {
        lsum[rh] += __shfl_xor_sync(0xffffffffu, lsum[rh], 1);
        lsum[rh] += __shfl_xor_sync(0xffffffffu, lsum[rh], 2);
    }
    float inv[2] = {1.0f / lsum[0], 1.0f / lsum[1]};
    #pragma unroll
    for (int ni2 = 0; ni2 < 4; ni2++) {
        #pragma unroll
        for (int n8p = 0; n8p < 2; n8p++) {
            int col = h * 64 + ni2 * 16 + n8p * 8 + t4 * 2;
            #pragma unroll
            for (int rh = 0; rh < 2; rh++) {
                size_t m = (size_t)b * SEQ + qb * 128 + w * 16 + g + rh * 8;
                float v0 = o[ni2][n8p][rh*2 + 0] * inv[rh];
                float v1 = o[ni2][n8p][rh*2 + 1] * inv[rh];
                uint32_t hiw, low;
                split2(v0, v1, hiw, low);
                *(uint32_t*)&g_Ahi[m * HID + col] = hiw;
                *(uint32_t*)&g_Alo[m * HID + col] = low;
            }
        }
    }
}

// ---------------- launch ----------------
extern "C" void kernel_launch(void* const* d_in, const int* in_sizes, int n_in,
                              void* d_out, int out_size)
{
    const float* x    = (const float*)d_in[0];
    const float* dist = (const float*)d_in[1];
    const unsigned char* mask = (const unsigned char*)d_in[2];
    const float* Wq = (const float*)d_in[3];
    const float* bq = (const float*)d_in[4];
    const float* Wk = (const float*)d_in[5];
    const float* bk = (const float*)d_in[6];
    const float* Wv = (const float*)d_in[7];
    const float* bv = (const float*)d_in[8];
    const float* Wo = (const float*)d_in[9];
    const float* bo = (const float*)d_in[10];
    const float* Wd = (const float*)d_in[11];
    const float* bd = (const float*)d_in[12];
    float* out = (float*)d_out;

    cudaFuncSetAttribute(fused_qkv_dist_kernel, cudaFuncAttributeMaxDynamicSharedMemorySize,
                         GEMM_SMEM_BYTES);
    cudaFuncSetAttribute(gemm_out_kernel, cudaFuncAttributeMaxDynamicSharedMemorySize,
                         GEMM3_SMEM_BYTES);
    cudaFuncSetAttribute(attn_mma_kernel, cudaFuncAttributeMaxDynamicSharedMemorySize,
                         ATTN_SMEM_BYTES);

    prep_x_kernel<<<2048, 256>>>(x);
    prep_w_kernel<<<1025, 256>>>(Wq, Wk, Wv, Wo, mask);
    fused_qkv_dist_kernel<<<8576, 256, GEMM_SMEM_BYTES>>>(bq, bk, bv, dist, Wd, bd);
    attn_mma_kernel<<<dim3(4, NH, NB), 256, ATTN_SMEM_BYTES>>>();
    gemm_out_kernel<<<dim3(4, 32), 256, GEMM3_SMEM_BYTES>>>(bo, out);
}